// round 8
// baseline (speedup 1.0000x reference)
#include <cuda_runtime.h>
#include <cuda_bf16.h>
#include <cstdint>

#define TSTEPS 16

// ---- SMEM layout (bytes) ----
#define SM_W      0                  // Wbuf[2 bufs][2 planes][256 rows][40 halves]
#define SM_AHI    81920              // [128][264] bf16
#define SM_ALO    149504             // [128][264] bf16
#define SM_BIAS   217088             // f32[1024] (m'-order)
#define SM_WLIN   221184             // f32[512]
#define SM_HEAD   223232             // f32[8][64][2]
#define SM_TOTAL  227328

// ---- device scratch ----
__device__ unsigned char g_Wimg[2][1048576];   // [ih/hh][32 chunks][hi 16KB | lo 16KB]
__device__ float    g_xproj[13107200];         // fragment-order x-projection (+bias)
__device__ float    g_cx[3276800];             // cell-order cell state
__device__ uint32_t g_hst[3276800];            // cell-order packed h (hi|lo bf16)

__device__ __forceinline__ uint32_t smem_u32(const void* p) {
    uint32_t a;
    asm("{ .reg .u64 t; cvta.to.shared.u64 t, %1; cvt.u32.u64 %0, t; }" : "=r"(a) : "l"(p));
    return a;
}
#define LDMX4(R, A) asm volatile( \
    "ldmatrix.sync.aligned.m8n8.x4.shared.b16 {%0,%1,%2,%3}, [%4];" \
    : "=r"((R)[0]), "=r"((R)[1]), "=r"((R)[2]), "=r"((R)[3]) : "r"(A))
#define MMA(D, A, B0, B1) asm volatile( \
    "mma.sync.aligned.m16n8k16.row.col.f32.bf16.bf16.f32 " \
    "{%0,%1,%2,%3}, {%4,%5,%6,%7}, {%8,%9}, {%0,%1,%2,%3};" \
    : "+f"((D)[0]), "+f"((D)[1]), "+f"((D)[2]), "+f"((D)[3]) \
    : "r"((A)[0]), "r"((A)[1]), "r"((A)[2]), "r"((A)[3]), "r"(B0), "r"(B1))
#define CPA16(S, G) asm volatile("cp.async.cg.shared.global [%0], [%1], 16;" :: "r"(S), "l"(G))
#define CPA_COMMIT() asm volatile("cp.async.commit_group;")
#define CPA_WAIT0()  asm volatile("cp.async.wait_group 0;")

__device__ __forceinline__ float fsig(float x) { return __fdividef(1.0f, 1.0f + __expf(-x)); }
__device__ __forceinline__ float ftanhx(float x) { return fmaf(2.0f, fsig(2.0f * x), -1.0f); }
__device__ __forceinline__ uint32_t pkbf(__nv_bfloat16 a, __nv_bfloat16 b) {
    return (uint32_t)__bfloat16_as_ushort(a) | ((uint32_t)__bfloat16_as_ushort(b) << 16);
}

// ---- prep: split W into hi/lo bf16 images, gate-interleaved (m' = 4j+g), chunked ----
__global__ void prep(const float* __restrict__ Wih, const float* __restrict__ Whh) {
    int id = blockIdx.x * 256 + threadIdx.x;       // 131072 threads
    int which = id >> 16;
    int rest  = id & 65535;
    int mp = rest >> 6;                            // m' 0..1023
    int k4 = (rest & 63) * 4;                      // k 0..252
    int j = mp >> 2, g = mp & 3;
    const float* W = which ? Whh : Wih;
    float4 v = *(const float4*)&W[(size_t)(g * 256 + j) * 256 + k4];
    int p = mp >> 8, q = mp & 255;
    int ck = k4 >> 5, kk = k4 & 31;
    size_t off = (size_t)(p * 8 + ck) * 32768 + (size_t)q * 64 + (size_t)kk * 2;
    float f[4] = {v.x, v.y, v.z, v.w};
    __nv_bfloat16 h[4], l[4];
    #pragma unroll
    for (int i = 0; i < 4; ++i) {
        h[i] = __float2bfloat16(f[i]);
        l[i] = __float2bfloat16(f[i] - __bfloat162float(h[i]));
    }
    unsigned char* dst = g_Wimg[which] + off;
    *(uint32_t*)(dst)           = pkbf(h[0], h[1]);
    *(uint32_t*)(dst + 4)       = pkbf(h[2], h[3]);
    *(uint32_t*)(dst + 16384)     = pkbf(l[0], l[1]);
    *(uint32_t*)(dst + 16384 + 4) = pkbf(l[2], l[3]);
}

// ---- main persistent kernel ----
__global__ void __launch_bounds__(256, 1)
lstm_mma(const float* __restrict__ x,
         const float* __restrict__ bih, const float* __restrict__ bhh,
         const float* __restrict__ Wlin, const float* __restrict__ blin,
         float* __restrict__ out)
{
    extern __shared__ unsigned char smem[];
    const uint32_t sb = smem_u32(smem);
    const int tid = threadIdx.x, l = tid & 31, w = tid >> 5;
    const int wr = w >> 2, wc = w & 3;
    const int cta = blockIdx.x, n0 = cta * 128;

    for (int i = tid; i < 1024; i += 256) {
        int j = i >> 2, g = i & 3;
        ((float*)(smem + SM_BIAS))[i] = bih[g * 256 + j] + bhh[g * 256 + j];
    }
    for (int i = tid; i < 512; i += 256) ((float*)(smem + SM_WLIN))[i] = Wlin[i];

    // A init: gather x row, split hi/lo
    {
        int r = tid >> 1, c0 = (tid & 1) * 128;
        int n = n0 + r, bb = n / 1600, hw = n % 1600;
        const float* xb = x + (size_t)bb * 409600 + hw;
        for (int cc = 0; cc < 128; ++cc) {
            int c = c0 + cc;
            float v = xb[(size_t)c * 1600];
            __nv_bfloat16 h = __float2bfloat16(v);
            __nv_bfloat16 lo = __float2bfloat16(v - __bfloat162float(h));
            *(uint16_t*)(smem + SM_AHI + (r * 264 + c) * 2) = __bfloat16_as_ushort(h);
            *(uint16_t*)(smem + SM_ALO + (r * 264 + c) * 2) = __bfloat16_as_ushort(lo);
        }
    }
    __syncthreads();

    // per-lane ldmatrix base addresses
    const uint32_t a_hi0 = sb + SM_AHI + (uint32_t)((wr * 64 + (l & 15)) * 264) * 2
                         + (uint32_t)((l >> 4) & 1) * 16;
    const uint32_t b_lane = (uint32_t)((wc * 64 + (l & 7) + ((l >> 4) & 1) * 8) * 80
                         + ((l >> 3) & 1) * 16);

    // prefetch chunk s of image img into buf
    auto prefetch = [&](int img, int s, int buf) {
        const unsigned char* src = g_Wimg[img] + (size_t)s * 32768;
        uint32_t dst = sb + SM_W + (uint32_t)buf * 40960;
        #pragma unroll
        for (int i = 0; i < 8; ++i) {
            int o = i * 256 + tid;
            int plane = o >> 10, rem = o & 1023;
            int q = rem >> 2, kq = rem & 3;
            CPA16(dst + plane * 20480 + q * 80 + kq * 16, src + (size_t)o * 16);
        }
        CPA_COMMIT();
    };

    const float bl0 = blin[0], bl1 = blin[1];
    prefetch(0, 0, 0);

    for (int t = 0; t < TSTEPS; ++t) {
        const int img = (t == 0) ? 0 : 1;
        float y0[4], y1[4];
        #pragma unroll
        for (int i = 0; i < 4; ++i) { y0[i] = 0.f; y1[i] = 0.f; }

        for (int p = 0; p < 4; ++p) {
            float acc[4][8][4];
            #pragma unroll
            for (int mf = 0; mf < 4; ++mf)
                #pragma unroll
                for (int nf = 0; nf < 8; ++nf)
                    #pragma unroll
                    for (int r4 = 0; r4 < 4; ++r4) acc[mf][nf][r4] = 0.f;

            for (int c = 0; c < 8; ++c) {
                int s = p * 8 + c, buf = s & 1;
                CPA_WAIT0();
                __syncthreads();
                int ns = s + 1;
                if (!(t == 15 && ns == 32))
                    prefetch(ns < 32 ? img : 1, ns & 31, buf ^ 1);
                const uint32_t wb_hi = sb + SM_W + (uint32_t)buf * 40960;
                #pragma unroll
                for (int kk = 0; kk < 2; ++kk) {
                    uint32_t ah[4][4], al[4][4];
                    #pragma unroll
                    for (int mf = 0; mf < 4; ++mf) {
                        uint32_t aa = a_hi0 + (uint32_t)(mf * 16 * 528) + (uint32_t)((c * 32 + kk * 16) * 2);
                        LDMX4(ah[mf], aa);
                        LDMX4(al[mf], aa + (SM_ALO - SM_AHI));
                    }
                    #pragma unroll
                    for (int half = 0; half < 2; ++half) {
                        uint32_t bh[2][4], bl[2][4];
                        #pragma unroll
                        for (int np = 0; np < 2; ++np) {
                            uint32_t ba = b_lane + (uint32_t)((half * 2 + np) * 16 * 80 + kk * 32);
                            LDMX4(bh[np], wb_hi + ba);
                            LDMX4(bl[np], wb_hi + 20480 + ba);
                        }
                        #pragma unroll
                        for (int mf = 0; mf < 4; ++mf)
                            #pragma unroll
                            for (int np = 0; np < 2; ++np)
                                #pragma unroll
                                for (int sub = 0; sub < 2; ++sub) {
                                    float* d = acc[mf][half * 4 + np * 2 + sub];
                                    MMA(d, ah[mf], bh[np][sub * 2], bh[np][sub * 2 + 1]);
                                    MMA(d, ah[mf], bl[np][sub * 2], bl[np][sub * 2 + 1]);
                                    MMA(d, al[mf], bh[np][sub * 2], bh[np][sub * 2 + 1]);
                                }
                    }
                }
            }

            // ---- epilogue for pass p ----
            const bool ifl = ((l & 1) == 0);    // lane holds i,f cols; partner holds g,o
            const size_t fb = ((size_t)((cta * 8 + w) * 4 + p));
            const size_t xpb = fb * 4096 + (size_t)l * 128;
            const size_t cxb = fb * 1024 + (size_t)l * 32;
            const float* sBias = (const float*)(smem + SM_BIAS);
            const float* sWl = (const float*)(smem + SM_WLIN);
            #pragma unroll
            for (int mf = 0; mf < 4; ++mf) {
                #pragma unroll
                for (int nf = 0; nf < 8; ++nf) {
                    float* d = acc[mf][nf];
                    float p0, p1, p2, p3;
                    if (t == 0) {
                        int m0 = p * 256 + wc * 64 + nf * 8 + 2 * (l & 3);
                        float bb0 = sBias[m0], bb1 = sBias[m0 + 1];
                        p0 = d[0] + bb0; p1 = d[1] + bb1; p2 = d[2] + bb0; p3 = d[3] + bb1;
                        float4 st = {p0, p1, p2, p3};
                        *(float4*)&g_xproj[xpb + (mf * 8 + nf) * 4] = st;
                    } else {
                        float4 xp = *(const float4*)&g_xproj[xpb + (mf * 8 + nf) * 4];
                        p0 = d[0] + xp.x; p1 = d[1] + xp.y; p2 = d[2] + xp.z; p3 = d[3] + xp.w;
                    }
                    float u0, u1, u2, u3;
                    if (ifl) { u0 = fsig(p0); u1 = fsig(p1); u2 = fsig(p2); u3 = fsig(p3); }
                    else     { u0 = ftanhx(p0); u1 = fsig(p1); u2 = ftanhx(p2); u3 = fsig(p3); }
                    // ifl lane keeps row r (sends r+8's i,f); go lane keeps row r+8 (sends r's g,o)
                    float s0 = ifl ? u2 : u0;
                    float s1 = ifl ? u3 : u1;
                    float r0 = __shfl_xor_sync(0xffffffffu, s0, 1);
                    float r1 = __shfl_xor_sync(0xffffffffu, s1, 1);
                    float ig, fg, gg, og;
                    if (ifl) { ig = u0; fg = u1; gg = r0; og = r1; }
                    else     { ig = r0; fg = r1; gg = u2; og = u3; }
                    float cp = (t == 0) ? 0.f : g_cx[cxb + mf * 8 + nf];
                    float cn = fmaf(fg, cp, ig * gg);
                    float h = og * ftanhx(cn);
                    float lh = (h > 0.f) ? h : 0.01f * h;
                    int jj = p * 64 + wc * 16 + nf * 2 + ((l >> 1) & 1);
                    y0[mf] = fmaf(lh, sWl[jj], y0[mf]);
                    y1[mf] = fmaf(lh, sWl[256 + jj], y1[mf]);
                    if (t < 15) {
                        g_cx[cxb + mf * 8 + nf] = cn;
                        __nv_bfloat16 hh = __float2bfloat16(h);
                        __nv_bfloat16 hl = __float2bfloat16(h - __bfloat162float(hh));
                        g_hst[cxb + mf * 8 + nf] = pkbf(hh, hl);
                    }
                }
            }
        } // passes

        // ---- head: reduce over lane pairs (l ^ 2), then over warp cols via SMEM ----
        #pragma unroll
        for (int mf = 0; mf < 4; ++mf) {
            y0[mf] += __shfl_xor_sync(0xffffffffu, y0[mf], 2);
            y1[mf] += __shfl_xor_sync(0xffffffffu, y1[mf], 2);
        }
        if ((l & 2) == 0) {
            #pragma unroll
            for (int mf = 0; mf < 4; ++mf) {
                int rl = mf * 16 + (l >> 2) + 8 * (l & 1);
                ((float*)(smem + SM_HEAD))[(w * 64 + rl) * 2 + 0] = y0[mf];
                ((float*)(smem + SM_HEAD))[(w * 64 + rl) * 2 + 1] = y1[mf];
            }
        }
        __syncthreads();
        {
            int row = tid >> 1, o = tid & 1;
            int wrr = row >> 6, rl = row & 63;
            float v = o ? bl1 : bl0;
            #pragma unroll
            for (int wcc = 0; wcc < 4; ++wcc)
                v += ((float*)(smem + SM_HEAD))[((wrr * 4 + wcc) * 64 + rl) * 2 + o];
            out[(size_t)(n0 + row) * 32 + t * 2 + o] = v;
        }

        // ---- rebuild A from staged h (all mma of this step finished) ----
        if (t < 15) {
            __syncthreads();
            const uint32_t* hs = g_hst + (size_t)cta * 32768;
            for (int it = 0; it < 128; ++it) {
                int i = it * 256 + tid;
                uint32_t hv = hs[i];
                int ww = i >> 12, pp = (i >> 10) & 3, ll = (i >> 5) & 31, fr = i & 31;
                int mf = fr >> 3, nf = fr & 7;
                int row = (ww >> 2) * 64 + mf * 16 + (ll >> 2) + 8 * (ll & 1);
                int jj = pp * 64 + (ww & 3) * 16 + nf * 2 + ((ll >> 1) & 1);
                *(uint16_t*)(smem + SM_AHI + (row * 264 + jj) * 2) = (uint16_t)(hv & 0xffff);
                *(uint16_t*)(smem + SM_ALO + (row * 264 + jj) * 2) = (uint16_t)(hv >> 16);
            }
            __syncthreads();
        }
    } // t
}

extern "C" void kernel_launch(void* const* d_in, const int* in_sizes, int n_in,
                              void* d_out, int out_size) {
    const float* x    = (const float*)d_in[0];
    const float* Wih  = (const float*)d_in[3];
    const float* Whh  = (const float*)d_in[4];
    const float* bih  = (const float*)d_in[5];
    const float* bhh  = (const float*)d_in[6];
    const float* Wlin = (const float*)d_in[7];
    const float* blin = (const float*)d_in[8];
    (void)in_sizes; (void)n_in; (void)out_size;
    prep<<<512, 256>>>(Wih, Whh);
    cudaFuncSetAttribute(lstm_mma, cudaFuncAttributeMaxDynamicSharedMemorySize, SM_TOTAL);
    lstm_mma<<<100, 256, SM_TOTAL>>>(x, bih, bhh, Wlin, blin, (float*)d_out);
}

// round 9
// speedup vs baseline: 2.0245x; 2.0245x over previous
#include <cuda_runtime.h>
#include <cuda_bf16.h>
#include <cstdint>

#define TSTEPS 16
#define NCTA   134
#define MROWS  96
#define NTHR   384

// ---- SMEM layout (bytes) ----
#define SM_W      0                   // W bufs: 2 x (2 planes x 256 rows x 80B)
#define SM_AHI    81920               // [96][264] bf16
#define SM_ALO    132608              // [96][264] bf16
#define SM_BIAS   183296              // f32[1024] m'-order
#define SM_WLIN   187392              // f32[512]
#define SM_HEAD   189440              // f32[12][32][2]
#define SM_TOTAL  192512

// ---- device scratch ----
__device__ unsigned char g_Wimg[2][1048576];     // [ih/hh][32 chunks][16KB hi|16KB lo]
__device__ float    g_xproj[13172736];           // fragment-order xproj(+bias)
__device__ float    g_cx[3293184];
__device__ uint32_t g_hst[3293184];              // packed h (hi|lo bf16)

__device__ __forceinline__ uint32_t smem_u32(const void* p) {
    uint32_t a;
    asm("{ .reg .u64 t; cvta.to.shared.u64 t, %1; cvt.u32.u64 %0, t; }" : "=r"(a) : "l"(p));
    return a;
}
#define LDMX4(R, A) asm volatile( \
    "ldmatrix.sync.aligned.m8n8.x4.shared.b16 {%0,%1,%2,%3}, [%4];" \
    : "=r"((R)[0]), "=r"((R)[1]), "=r"((R)[2]), "=r"((R)[3]) : "r"(A))
#define MMA(D, A, B0, B1) asm volatile( \
    "mma.sync.aligned.m16n8k16.row.col.f32.bf16.bf16.f32 " \
    "{%0,%1,%2,%3}, {%4,%5,%6,%7}, {%8,%9}, {%0,%1,%2,%3};" \
    : "+f"((D)[0]), "+f"((D)[1]), "+f"((D)[2]), "+f"((D)[3]) \
    : "r"((A)[0]), "r"((A)[1]), "r"((A)[2]), "r"((A)[3]), "r"(B0), "r"(B1))
#define CPA16(S, G) asm volatile("cp.async.cg.shared.global [%0], [%1], 16;" :: "r"(S), "l"(G))
#define CPA_COMMIT() asm volatile("cp.async.commit_group;")
#define CPA_WAIT0()  asm volatile("cp.async.wait_group 0;")

__device__ __forceinline__ float fsig(float x) { return __fdividef(1.0f, 1.0f + __expf(-x)); }
__device__ __forceinline__ float ftanhx(float x) { return fmaf(2.0f, fsig(2.0f * x), -1.0f); }
__device__ __forceinline__ uint32_t pkbf(__nv_bfloat16 a, __nv_bfloat16 b) {
    return (uint32_t)__bfloat16_as_ushort(a) | ((uint32_t)__bfloat16_as_ushort(b) << 16);
}

// ---- prep: split W into hi/lo bf16 images, gate-interleaved (m' = 4j+g), 32KB chunks ----
__global__ void prep(const float* __restrict__ Wih, const float* __restrict__ Whh) {
    int id = blockIdx.x * 256 + threadIdx.x;       // 131072
    int which = id >> 16, rest = id & 65535;
    int mp = rest >> 6, k4 = (rest & 63) * 4;
    int j = mp >> 2, g = mp & 3;
    const float* W = which ? Whh : Wih;
    float4 v = *(const float4*)&W[(size_t)(g * 256 + j) * 256 + k4];
    int p = mp >> 8, q = mp & 255;
    int ck = k4 >> 5, kk = k4 & 31;
    size_t off = (size_t)(p * 8 + ck) * 32768 + (size_t)q * 64 + (size_t)kk * 2;
    float f[4] = {v.x, v.y, v.z, v.w};
    __nv_bfloat16 h[4], l[4];
    #pragma unroll
    for (int i = 0; i < 4; ++i) {
        h[i] = __float2bfloat16(f[i]);
        l[i] = __float2bfloat16(f[i] - __bfloat162float(h[i]));
    }
    unsigned char* dst = g_Wimg[which] + off;
    *(uint32_t*)(dst)             = pkbf(h[0], h[1]);
    *(uint32_t*)(dst + 4)         = pkbf(h[2], h[3]);
    *(uint32_t*)(dst + 16384)     = pkbf(l[0], l[1]);
    *(uint32_t*)(dst + 16384 + 4) = pkbf(l[2], l[3]);
}

__global__ void __launch_bounds__(NTHR, 1)
lstm_mma(const float* __restrict__ x,
         const float* __restrict__ bih, const float* __restrict__ bhh,
         const float* __restrict__ Wlin, const float* __restrict__ blin,
         float* __restrict__ out)
{
    extern __shared__ unsigned char smem[];
    const uint32_t sb = smem_u32(smem);
    const int tid = threadIdx.x, l = tid & 31, w = tid >> 5;
    const int wr = w >> 2, wc = w & 3;
    const int cta = blockIdx.x, n0 = cta * MROWS;

    for (int i = tid; i < 1024; i += NTHR) {
        int j = i >> 2, g = i & 3;
        ((float*)(smem + SM_BIAS))[i] = bih[g * 256 + j] + bhh[g * 256 + j];
    }
    for (int i = tid; i < 512; i += NTHR) ((float*)(smem + SM_WLIN))[i] = Wlin[i];

    // A init: gather x rows (clamped), split hi/lo
    {
        int r = tid >> 2, c0 = (tid & 3) * 64;
        int n = n0 + r; if (n > 12799) n = 12799;
        int bb = n / 1600, hw = n % 1600;
        const float* xb = x + (size_t)bb * 409600 + hw;
        for (int cc = 0; cc < 64; ++cc) {
            int c = c0 + cc;
            float v = xb[(size_t)c * 1600];
            __nv_bfloat16 h = __float2bfloat16(v);
            __nv_bfloat16 lo = __float2bfloat16(v - __bfloat162float(h));
            *(uint16_t*)(smem + SM_AHI + (r * 264 + c) * 2) = __bfloat16_as_ushort(h);
            *(uint16_t*)(smem + SM_ALO + (r * 264 + c) * 2) = __bfloat16_as_ushort(lo);
        }
    }
    __syncthreads();

    const uint32_t a_hi0 = sb + SM_AHI + (uint32_t)((wr * 32 + (l & 15)) * 264) * 2
                         + (uint32_t)((l >> 4) & 1) * 16;
    const uint32_t b_lane = (uint32_t)((wc * 64 + (l & 7) + ((l >> 4) & 1) * 8) * 80
                         + ((l >> 3) & 1) * 16);

    auto prefetch = [&](int img, int s, int buf) {
        const unsigned char* src = g_Wimg[img] + (size_t)s * 32768;
        uint32_t dst = sb + SM_W + (uint32_t)buf * 40960;
        #pragma unroll
        for (int i = 0; i < 6; ++i) {
            int o = i * NTHR + tid;
            if (o < 2048) {
                int plane = o >> 10, rem = o & 1023;
                CPA16(dst + plane * 20480 + (rem >> 2) * 80 + (rem & 3) * 16,
                      src + (size_t)o * 16);
            }
        }
        CPA_COMMIT();
    };

    const float bl0 = blin[0], bl1 = blin[1];
    prefetch(0, 0, 0);

    for (int t = 0; t < TSTEPS; ++t) {
        const int img = (t == 0) ? 0 : 1;
        float y0[2] = {0.f, 0.f}, y1[2] = {0.f, 0.f};

        for (int p = 0; p < 4; ++p) {
            float acc[2][8][4];
            #pragma unroll
            for (int mf = 0; mf < 2; ++mf)
                #pragma unroll
                for (int nf = 0; nf < 8; ++nf)
                    #pragma unroll
                    for (int r4 = 0; r4 < 4; ++r4) acc[mf][nf][r4] = 0.f;

            for (int c = 0; c < 8; ++c) {
                int s = p * 8 + c, buf = s & 1;
                CPA_WAIT0();
                __syncthreads();
                int ns = s + 1;
                if (!(t == 15 && ns == 32))
                    prefetch(ns < 32 ? img : 1, ns & 31, buf ^ 1);
                const uint32_t wb_hi = sb + SM_W + (uint32_t)buf * 40960;
                #pragma unroll
                for (int kk = 0; kk < 2; ++kk) {
                    uint32_t ah[2][4], al[2][4];
                    #pragma unroll
                    for (int mf = 0; mf < 2; ++mf) {
                        uint32_t aa = a_hi0 + (uint32_t)(mf * 16 * 528)
                                    + (uint32_t)((c * 32 + kk * 16) * 2);
                        LDMX4(ah[mf], aa);
                        LDMX4(al[mf], aa + (SM_ALO - SM_AHI));
                    }
                    #pragma unroll
                    for (int half = 0; half < 2; ++half) {
                        uint32_t bh[2][4], bl[2][4];
                        #pragma unroll
                        for (int np = 0; np < 2; ++np) {
                            uint32_t ba = b_lane + (uint32_t)((half * 2 + np) * 16 * 80 + kk * 32);
                            LDMX4(bh[np], wb_hi + ba);
                            LDMX4(bl[np], wb_hi + 20480 + ba);
                        }
                        #pragma unroll
                        for (int mf = 0; mf < 2; ++mf)
                            #pragma unroll
                            for (int np = 0; np < 2; ++np)
                                #pragma unroll
                                for (int sub = 0; sub < 2; ++sub) {
                                    float* d = acc[mf][half * 4 + np * 2 + sub];
                                    MMA(d, ah[mf], bh[np][sub * 2], bh[np][sub * 2 + 1]);
                                    MMA(d, ah[mf], bl[np][sub * 2], bl[np][sub * 2 + 1]);
                                    MMA(d, al[mf], bh[np][sub * 2], bh[np][sub * 2 + 1]);
                                }
                    }
                }
            }

            // ---- epilogue for pass p ----
            const bool ifl = ((l & 1) == 0);
            const float* sBias = (const float*)(smem + SM_BIAS);
            const float* sWl = (const float*)(smem + SM_WLIN);
            #pragma unroll
            for (int mf = 0; mf < 2; ++mf) {
                const size_t base = ((((size_t)(cta * 12 + w) * 4 + p) * 2 + mf));
                const size_t xpb = base * 1024;
                const size_t cxb = base * 256;
                #pragma unroll
                for (int nf = 0; nf < 8; ++nf) {
                    float* d = acc[mf][nf];
                    float p0, p1, p2, p3;
                    if (t == 0) {
                        int m0 = p * 256 + wc * 64 + nf * 8 + 2 * (l & 3);
                        float bb0 = sBias[m0], bb1 = sBias[m0 + 1];
                        p0 = d[0] + bb0; p1 = d[1] + bb1; p2 = d[2] + bb0; p3 = d[3] + bb1;
                        float4 st = {p0, p1, p2, p3};
                        *(float4*)&g_xproj[xpb + (size_t)(nf * 32 + l) * 4] = st;
                    } else {
                        float4 xp = *(const float4*)&g_xproj[xpb + (size_t)(nf * 32 + l) * 4];
                        p0 = d[0] + xp.x; p1 = d[1] + xp.y; p2 = d[2] + xp.z; p3 = d[3] + xp.w;
                    }
                    float u0, u1, u2, u3;
                    if (ifl) { u0 = fsig(p0); u1 = fsig(p1); u2 = fsig(p2); u3 = fsig(p3); }
                    else     { u0 = ftanhx(p0); u1 = fsig(p1); u2 = ftanhx(p2); u3 = fsig(p3); }
                    float s0 = ifl ? u2 : u0;
                    float s1 = ifl ? u3 : u1;
                    float r0 = __shfl_xor_sync(0xffffffffu, s0, 1);
                    float r1 = __shfl_xor_sync(0xffffffffu, s1, 1);
                    float ig, fg, gg, og;
                    if (ifl) { ig = u0; fg = u1; gg = r0; og = r1; }
                    else     { ig = r0; fg = r1; gg = u2; og = u3; }
                    float cp = (t == 0) ? 0.f : g_cx[cxb + nf * 32 + l];
                    float cn = fmaf(fg, cp, ig * gg);
                    float h = og * ftanhx(cn);
                    float lh = (h > 0.f) ? h : 0.01f * h;
                    int jj = p * 64 + wc * 16 + nf * 2 + ((l >> 1) & 1);
                    y0[mf] = fmaf(lh, sWl[jj], y0[mf]);
                    y1[mf] = fmaf(lh, sWl[256 + jj], y1[mf]);
                    if (t < 15) {
                        g_cx[cxb + nf * 32 + l] = cn;
                        __nv_bfloat16 hh = __float2bfloat16(h);
                        __nv_bfloat16 hl = __float2bfloat16(h - __bfloat162float(hh));
                        g_hst[cxb + nf * 32 + l] = pkbf(hh, hl);
                    }
                }
            }
        } // passes

        // ---- head: reduce lane pairs (l^2), then col-warps via SMEM ----
        #pragma unroll
        for (int mf = 0; mf < 2; ++mf) {
            y0[mf] += __shfl_xor_sync(0xffffffffu, y0[mf], 2);
            y1[mf] += __shfl_xor_sync(0xffffffffu, y1[mf], 2);
        }
        if ((l & 2) == 0) {
            #pragma unroll
            for (int mf = 0; mf < 2; ++mf) {
                int rl = mf * 16 + (l >> 2) + 8 * (l & 1);
                ((float*)(smem + SM_HEAD))[(w * 32 + rl) * 2 + 0] = y0[mf];
                ((float*)(smem + SM_HEAD))[(w * 32 + rl) * 2 + 1] = y1[mf];
            }
        }
        __syncthreads();
        if (tid < 192) {
            int row = tid >> 1, o = tid & 1;
            int wrr = row >> 5, rl = row & 31;
            int n = n0 + row;
            if (n < 12800) {
                float v = o ? bl1 : bl0;
                #pragma unroll
                for (int wcc = 0; wcc < 4; ++wcc)
                    v += ((float*)(smem + SM_HEAD))[((wrr * 4 + wcc) * 32 + rl) * 2 + o];
                out[(size_t)n * 32 + t * 2 + o] = v;
            }
        }

        // ---- rebuild A from staged h ----
        if (t < 15) {
            __syncthreads();
            const uint32_t* hs = g_hst + (size_t)cta * 24576;
            #pragma unroll
            for (int it = 0; it < 64; ++it) {
                int i = it * NTHR + tid;
                uint32_t hv = hs[i];
                int ww = i >> 11, pp = (i >> 9) & 3, mf = (i >> 8) & 1;
                int nf = (i >> 5) & 7, ll = i & 31;
                int row = (ww >> 2) * 32 + mf * 16 + (ll >> 2) + 8 * (ll & 1);
                int jj = pp * 64 + (ww & 3) * 16 + nf * 2 + ((ll >> 1) & 1);
                *(uint16_t*)(smem + SM_AHI + (row * 264 + jj) * 2) = (uint16_t)(hv & 0xffff);
                *(uint16_t*)(smem + SM_ALO + (row * 264 + jj) * 2) = (uint16_t)(hv >> 16);
            }
            __syncthreads();
        }
    } // t
}

extern "C" void kernel_launch(void* const* d_in, const int* in_sizes, int n_in,
                              void* d_out, int out_size) {
    const float* x    = (const float*)d_in[0];
    const float* Wih  = (const float*)d_in[3];
    const float* Whh  = (const float*)d_in[4];
    const float* bih  = (const float*)d_in[5];
    const float* bhh  = (const float*)d_in[6];
    const float* Wlin = (const float*)d_in[7];
    const float* blin = (const float*)d_in[8];
    (void)in_sizes; (void)n_in; (void)out_size;
    prep<<<512, 256>>>(Wih, Whh);
    cudaFuncSetAttribute(lstm_mma, cudaFuncAttributeMaxDynamicSharedMemorySize, SM_TOTAL);
    lstm_mma<<<NCTA, NTHR, SM_TOTAL>>>(x, bih, bhh, Wlin, blin, (float*)d_out);
}

// round 10
// speedup vs baseline: 2.3148x; 1.1434x over previous
#include <cuda_runtime.h>
#include <cuda_fp16.h>
#include <cstdint>

#define TSTEPS 16
#define NCTA   134
#define MROWS  96
#define NTHR   384

// ---- SMEM layout (bytes) ----
#define SM_W      0                   // 4 bufs x (2 planes x 256 rows x 80B)
#define SM_AHI    163840              // [96][264] fp16
#define SM_BIAS   214528              // f32[1024] m'-order
#define SM_WLIN   218624              // f32[512]
#define SM_HEAD   220672              // f32[12][32][2]
#define SM_TOTAL  223744

// ---- device scratch ----
__device__ unsigned char g_Wimg[2][1048576];     // [ih/hh][32 chunks][16KB hi|16KB lo]
__device__ float    g_xproj[13172736];           // fragment-order xproj(+bias)
__device__ float    g_cx[3293184];
__device__ uint16_t g_hst[3293184];              // fp16 h staging

__device__ __forceinline__ uint32_t smem_u32(const void* p) {
    uint32_t a;
    asm("{ .reg .u64 t; cvta.to.shared.u64 t, %1; cvt.u32.u64 %0, t; }" : "=r"(a) : "l"(p));
    return a;
}
#define LDMX4(R, A) asm volatile( \
    "ldmatrix.sync.aligned.m8n8.x4.shared.b16 {%0,%1,%2,%3}, [%4];" \
    : "=r"((R)[0]), "=r"((R)[1]), "=r"((R)[2]), "=r"((R)[3]) : "r"(A))
#define MMA(D, A, B0, B1) asm volatile( \
    "mma.sync.aligned.m16n8k16.row.col.f32.f16.f16.f32 " \
    "{%0,%1,%2,%3}, {%4,%5,%6,%7}, {%8,%9}, {%0,%1,%2,%3};" \
    : "+f"((D)[0]), "+f"((D)[1]), "+f"((D)[2]), "+f"((D)[3]) \
    : "r"((A)[0]), "r"((A)[1]), "r"((A)[2]), "r"((A)[3]), "r"(B0), "r"(B1))
#define CPA16(S, G) asm volatile("cp.async.cg.shared.global [%0], [%1], 16;" :: "r"(S), "l"(G))
#define CPA_COMMIT() asm volatile("cp.async.commit_group;")
#define CPA_WAIT0()  asm volatile("cp.async.wait_group 0;")
#define CPA_WAIT2()  asm volatile("cp.async.wait_group 2;")

__device__ __forceinline__ float fsig(float x) { return __fdividef(1.0f, 1.0f + __expf(-x)); }
__device__ __forceinline__ float ftanhx(float x) { return fmaf(2.0f, fsig(2.0f * x), -1.0f); }
__device__ __forceinline__ uint32_t pkh(__half a, __half b) {
    return (uint32_t)__half_as_ushort(a) | ((uint32_t)__half_as_ushort(b) << 16);
}

// ---- prep: split W into fp16 hi/lo images, gate-interleaved (m' = 4j+g), 32KB chunks ----
__global__ void prep(const float* __restrict__ Wih, const float* __restrict__ Whh) {
    int id = blockIdx.x * 256 + threadIdx.x;       // 131072
    int which = id >> 16, rest = id & 65535;
    int mp = rest >> 6, k4 = (rest & 63) * 4;
    int j = mp >> 2, g = mp & 3;
    const float* W = which ? Whh : Wih;
    float4 v = *(const float4*)&W[(size_t)(g * 256 + j) * 256 + k4];
    int p = mp >> 8, q = mp & 255;
    int ck = k4 >> 5, kk = k4 & 31;
    size_t off = (size_t)(p * 8 + ck) * 32768 + (size_t)q * 64 + (size_t)kk * 2;
    float f[4] = {v.x, v.y, v.z, v.w};
    __half h[4], l[4];
    #pragma unroll
    for (int i = 0; i < 4; ++i) {
        h[i] = __float2half_rn(f[i]);
        l[i] = __float2half_rn(f[i] - __half2float(h[i]));
    }
    unsigned char* dst = g_Wimg[which] + off;
    *(uint32_t*)(dst)             = pkh(h[0], h[1]);
    *(uint32_t*)(dst + 4)         = pkh(h[2], h[3]);
    *(uint32_t*)(dst + 16384)     = pkh(l[0], l[1]);
    *(uint32_t*)(dst + 16384 + 4) = pkh(l[2], l[3]);
}

__global__ void __launch_bounds__(NTHR, 1)
lstm_mma(const float* __restrict__ x,
         const float* __restrict__ bih, const float* __restrict__ bhh,
         const float* __restrict__ Wlin, const float* __restrict__ blin,
         float* __restrict__ out)
{
    extern __shared__ unsigned char smem[];
    const uint32_t sb = smem_u32(smem);
    const int tid = threadIdx.x, l = tid & 31, w = tid >> 5;
    const int wr = w >> 2, wc = w & 3;
    const int cta = blockIdx.x, n0 = cta * MROWS;

    for (int i = tid; i < 1024; i += NTHR) {
        int j = i >> 2, g = i & 3;
        ((float*)(smem + SM_BIAS))[i] = bih[g * 256 + j] + bhh[g * 256 + j];
    }
    for (int i = tid; i < 512; i += NTHR) ((float*)(smem + SM_WLIN))[i] = Wlin[i];

    // A init: gather x rows (clamped), fp16
    {
        int r = tid >> 2, c0 = (tid & 3) * 64;
        int n = n0 + r; if (n > 12799) n = 12799;
        int bb = n / 1600, hw = n % 1600;
        const float* xb = x + (size_t)bb * 409600 + hw;
        for (int cc = 0; cc < 64; ++cc) {
            int c = c0 + cc;
            float v = xb[(size_t)c * 1600];
            *(uint16_t*)(smem + SM_AHI + (r * 264 + c) * 2) =
                __half_as_ushort(__float2half_rn(v));
        }
    }

    const uint32_t a_hi0 = sb + SM_AHI + (uint32_t)((wr * 32 + (l & 15)) * 264) * 2
                         + (uint32_t)((l >> 4) & 1) * 16;
    const uint32_t b_lane = (uint32_t)((wc * 64 + (l & 7) + ((l >> 4) & 1) * 8) * 80
                         + ((l >> 3) & 1) * 16);

    auto prefetch = [&](int img, int s, int buf) {
        const unsigned char* src = g_Wimg[img] + (size_t)s * 32768;
        uint32_t dst = sb + SM_W + (uint32_t)buf * 40960;
        #pragma unroll
        for (int i = 0; i < 6; ++i) {
            int o = i * NTHR + tid;
            if (o < 2048) {
                int plane = o >> 10, rem = o & 1023;
                CPA16(dst + plane * 20480 + (rem >> 2) * 80 + (rem & 3) * 16,
                      src + (size_t)o * 16);
            }
        }
        CPA_COMMIT();
    };

    const float bl0 = blin[0], bl1 = blin[1];
    prefetch(0, 0, 0);
    prefetch(0, 1, 1);
    __syncthreads();

    for (int t = 0; t < TSTEPS; ++t) {
        const int img = (t == 0) ? 0 : 1;
        float y0[2] = {0.f, 0.f}, y1[2] = {0.f, 0.f};

        for (int p = 0; p < 4; ++p) {
            float acc[2][8][4];
            #pragma unroll
            for (int mf = 0; mf < 2; ++mf)
                #pragma unroll
                for (int nf = 0; nf < 8; ++nf)
                    #pragma unroll
                    for (int r4 = 0; r4 < 4; ++r4) acc[mf][nf][r4] = 0.f;

            for (int cc = 0; cc < 4; ++cc) {
                int s0 = p * 8 + cc * 2;
                __syncthreads();
                if (!(t == 15 && s0 == 30)) {
                    int n1 = s0 + 2, n2 = s0 + 3;
                    prefetch(n1 < 32 ? img : 1, n1 & 31, n1 & 3);
                    prefetch(n2 < 32 ? img : 1, n2 & 31, n2 & 3);
                    CPA_WAIT2();
                } else {
                    CPA_WAIT0();
                }
                #pragma unroll
                for (int cs = 0; cs < 2; ++cs) {
                    int s = s0 + cs;
                    const uint32_t wb = sb + SM_W + (uint32_t)(s & 3) * 40960;
                    #pragma unroll
                    for (int kk = 0; kk < 2; ++kk) {
                        uint32_t ah[2][4];
                        #pragma unroll
                        for (int mf = 0; mf < 2; ++mf) {
                            uint32_t aa = a_hi0 + (uint32_t)(mf * 16 * 528)
                                        + (uint32_t)(((s & 7) * 32 + kk * 16) * 2);
                            LDMX4(ah[mf], aa);
                        }
                        #pragma unroll
                        for (int half = 0; half < 2; ++half) {
                            uint32_t bh[2][4], bl[2][4];
                            #pragma unroll
                            for (int np = 0; np < 2; ++np) {
                                uint32_t ba = b_lane + (uint32_t)((half * 2 + np) * 16 * 80 + kk * 32);
                                LDMX4(bh[np], wb + ba);
                                LDMX4(bl[np], wb + 20480 + ba);
                            }
                            #pragma unroll
                            for (int mf = 0; mf < 2; ++mf)
                                #pragma unroll
                                for (int np = 0; np < 2; ++np)
                                    #pragma unroll
                                    for (int sub = 0; sub < 2; ++sub) {
                                        float* d = acc[mf][half * 4 + np * 2 + sub];
                                        MMA(d, ah[mf], bh[np][sub * 2], bh[np][sub * 2 + 1]);
                                        MMA(d, ah[mf], bl[np][sub * 2], bl[np][sub * 2 + 1]);
                                    }
                        }
                    }
                }
            }

            // ---- epilogue for pass p ----
            const bool ifl = ((l & 1) == 0);
            const float* sBias = (const float*)(smem + SM_BIAS);
            const float* sWl = (const float*)(smem + SM_WLIN);
            #pragma unroll
            for (int mf = 0; mf < 2; ++mf) {
                const size_t base = ((((size_t)(cta * 12 + w) * 4 + p) * 2 + mf));
                const size_t xpb = base * 1024;
                const size_t cxb = base * 256;
                #pragma unroll
                for (int nf = 0; nf < 8; ++nf) {
                    float* d = acc[mf][nf];
                    float p0, p1, p2, p3;
                    if (t == 0) {
                        int m0 = p * 256 + wc * 64 + nf * 8 + 2 * (l & 3);
                        float bb0 = sBias[m0], bb1 = sBias[m0 + 1];
                        p0 = d[0] + bb0; p1 = d[1] + bb1; p2 = d[2] + bb0; p3 = d[3] + bb1;
                        float4 st = {p0, p1, p2, p3};
                        *(float4*)&g_xproj[xpb + (size_t)(nf * 32 + l) * 4] = st;
                    } else {
                        float4 xp = *(const float4*)&g_xproj[xpb + (size_t)(nf * 32 + l) * 4];
                        p0 = d[0] + xp.x; p1 = d[1] + xp.y; p2 = d[2] + xp.z; p3 = d[3] + xp.w;
                    }
                    float u0, u1, u2, u3;
                    if (ifl) { u0 = fsig(p0); u1 = fsig(p1); u2 = fsig(p2); u3 = fsig(p3); }
                    else     { u0 = ftanhx(p0); u1 = fsig(p1); u2 = ftanhx(p2); u3 = fsig(p3); }
                    float s0 = ifl ? u2 : u0;
                    float s1 = ifl ? u3 : u1;
                    float r0 = __shfl_xor_sync(0xffffffffu, s0, 1);
                    float r1 = __shfl_xor_sync(0xffffffffu, s1, 1);
                    float ig, fg, gg, og;
                    if (ifl) { ig = u0; fg = u1; gg = r0; og = r1; }
                    else     { ig = r0; fg = r1; gg = u2; og = u3; }
                    float cp = (t == 0) ? 0.f : g_cx[cxb + nf * 32 + l];
                    float cn = fmaf(fg, cp, ig * gg);
                    float h = og * ftanhx(cn);
                    float lh = (h > 0.f) ? h : 0.01f * h;
                    int jj = p * 64 + wc * 16 + nf * 2 + ((l >> 1) & 1);
                    y0[mf] = fmaf(lh, sWl[jj], y0[mf]);
                    y1[mf] = fmaf(lh, sWl[256 + jj], y1[mf]);
                    if (t < 15) {
                        g_cx[cxb + nf * 32 + l] = cn;
                        g_hst[cxb + nf * 32 + l] = __half_as_ushort(__float2half_rn(h));
                    }
                }
            }
        } // passes

        // ---- head: reduce lane pairs (l^2), then col-warps via SMEM ----
        #pragma unroll
        for (int mf = 0; mf < 2; ++mf) {
            y0[mf] += __shfl_xor_sync(0xffffffffu, y0[mf], 2);
            y1[mf] += __shfl_xor_sync(0xffffffffu, y1[mf], 2);
        }
        if ((l & 2) == 0) {
            #pragma unroll
            for (int mf = 0; mf < 2; ++mf) {
                int rl = mf * 16 + (l >> 2) + 8 * (l & 1);
                ((float*)(smem + SM_HEAD))[(w * 32 + rl) * 2 + 0] = y0[mf];
                ((float*)(smem + SM_HEAD))[(w * 32 + rl) * 2 + 1] = y1[mf];
            }
        }
        __syncthreads();
        if (tid < 192) {
            int row = tid >> 1, o = tid & 1;
            int wrr = row >> 5, rl = row & 31;
            int n = n0 + row;
            if (n < 12800) {
                float v = o ? bl1 : bl0;
                #pragma unroll
                for (int wcc = 0; wcc < 4; ++wcc)
                    v += ((float*)(smem + SM_HEAD))[((wrr * 4 + wcc) * 32 + rl) * 2 + o];
                out[(size_t)n * 32 + t * 2 + o] = v;
            }
        }

        // ---- rebuild A (fp16) from staged h ----
        if (t < 15) {
            __syncthreads();
            const uint16_t* hs = g_hst + (size_t)cta * 24576;
            #pragma unroll
            for (int it = 0; it < 64; ++it) {
                int i = it * NTHR + tid;
                uint16_t hv = hs[i];
                int ww = i >> 11, pp = (i >> 9) & 3, mf = (i >> 8) & 1;
                int nf = (i >> 5) & 7, ll = i & 31;
                int row = (ww >> 2) * 32 + mf * 16 + (ll >> 2) + 8 * (ll & 1);
                int jj = pp * 64 + (ww & 3) * 16 + nf * 2 + ((ll >> 1) & 1);
                *(uint16_t*)(smem + SM_AHI + (row * 264 + jj) * 2) = hv;
            }
        }
    } // t
}

extern "C" void kernel_launch(void* const* d_in, const int* in_sizes, int n_in,
                              void* d_out, int out_size) {
    const float* x    = (const float*)d_in[0];
    const float* Wih  = (const float*)d_in[3];
    const float* Whh  = (const float*)d_in[4];
    const float* bih  = (const float*)d_in[5];
    const float* bhh  = (const float*)d_in[6];
    const float* Wlin = (const float*)d_in[7];
    const float* blin = (const float*)d_in[8];
    (void)in_sizes; (void)n_in; (void)out_size;
    prep<<<512, 256>>>(Wih, Whh);
    cudaFuncSetAttribute(lstm_mma, cudaFuncAttributeMaxDynamicSharedMemorySize, SM_TOTAL);
    lstm_mma<<<NCTA, NTHR, SM_TOTAL>>>(x, bih, bhh, Wlin, blin, (float*)d_out);
}

// round 11
// speedup vs baseline: 2.6173x; 1.1307x over previous
#include <cuda_runtime.h>
#include <cuda_fp16.h>
#include <cstdint>

#define TSTEPS 16
#define NCTA   268
#define MROWS  48
#define NTHR   256

// ---- SMEM layout (bytes), 113408 total -> 2 CTAs/SM ----
#define SM_W      0                   // 2 bufs x (2 planes x 256 rows x 80B)
#define SM_A      81920               // [48][264] fp16
#define SM_BIAS   107264              // f32[1024] m'-order; HEAD overlays (3072B)
#define SM_WLIN   111360              // f32[512]
#define SM_TOTAL  113408
#define SM_HEAD   SM_BIAS

// ---- device scratch ----
__device__ unsigned char g_Wimg[2][1048576];     // [ih/hh][32 chunks][16KB hi|16KB lo]
__device__ float    g_xproj[13172736];           // fragment-order xproj(+bias)
__device__ float    g_cx[3293184];
__device__ uint16_t g_hst[3293184];              // fp16 h staging

__device__ __forceinline__ uint32_t smem_u32(const void* p) {
    uint32_t a;
    asm("{ .reg .u64 t; cvta.to.shared.u64 t, %1; cvt.u32.u64 %0, t; }" : "=r"(a) : "l"(p));
    return a;
}
#define LDMX4(R, A) asm volatile( \
    "ldmatrix.sync.aligned.m8n8.x4.shared.b16 {%0,%1,%2,%3}, [%4];" \
    : "=r"((R)[0]), "=r"((R)[1]), "=r"((R)[2]), "=r"((R)[3]) : "r"(A))
#define MMA(D, A, B0, B1) asm volatile( \
    "mma.sync.aligned.m16n8k16.row.col.f32.f16.f16.f32 " \
    "{%0,%1,%2,%3}, {%4,%5,%6,%7}, {%8,%9}, {%0,%1,%2,%3};" \
    : "+f"((D)[0]), "+f"((D)[1]), "+f"((D)[2]), "+f"((D)[3]) \
    : "r"((A)[0]), "r"((A)[1]), "r"((A)[2]), "r"((A)[3]), "r"(B0), "r"(B1))
#define CPA16(S, G) asm volatile("cp.async.cg.shared.global [%0], [%1], 16;" :: "r"(S), "l"(G))
#define CPA_COMMIT() asm volatile("cp.async.commit_group;")
#define CPA_WAIT0()  asm volatile("cp.async.wait_group 0;")
#define CPA_WAIT1()  asm volatile("cp.async.wait_group 1;")

__device__ __forceinline__ float fsig(float x) { return __fdividef(1.0f, 1.0f + __expf(-x)); }
__device__ __forceinline__ float ftanhx(float x) { return fmaf(2.0f, fsig(2.0f * x), -1.0f); }
__device__ __forceinline__ uint32_t pkh(__half a, __half b) {
    return (uint32_t)__half_as_ushort(a) | ((uint32_t)__half_as_ushort(b) << 16);
}

// ---- prep: split W into fp16 hi/lo images, gate-interleaved (m' = 4j+g), 32KB chunks ----
__global__ void prep(const float* __restrict__ Wih, const float* __restrict__ Whh) {
    int id = blockIdx.x * 256 + threadIdx.x;       // 131072
    int which = id >> 16, rest = id & 65535;
    int mp = rest >> 6, k4 = (rest & 63) * 4;
    int j = mp >> 2, g = mp & 3;
    const float* W = which ? Whh : Wih;
    float4 v = *(const float4*)&W[(size_t)(g * 256 + j) * 256 + k4];
    int p = mp >> 8, q = mp & 255;
    int ck = k4 >> 5, kk = k4 & 31;
    size_t off = (size_t)(p * 8 + ck) * 32768 + (size_t)q * 64 + (size_t)kk * 2;
    float f[4] = {v.x, v.y, v.z, v.w};
    __half h[4], l[4];
    #pragma unroll
    for (int i = 0; i < 4; ++i) {
        h[i] = __float2half_rn(f[i]);
        l[i] = __float2half_rn(f[i] - __half2float(h[i]));
    }
    unsigned char* dst = g_Wimg[which] + off;
    *(uint32_t*)(dst)             = pkh(h[0], h[1]);
    *(uint32_t*)(dst + 4)         = pkh(h[2], h[3]);
    *(uint32_t*)(dst + 16384)     = pkh(l[0], l[1]);
    *(uint32_t*)(dst + 16384 + 4) = pkh(l[2], l[3]);
}

__global__ void __launch_bounds__(NTHR, 2)
lstm_mma(const float* __restrict__ x,
         const float* __restrict__ bih, const float* __restrict__ bhh,
         const float* __restrict__ Wlin, const float* __restrict__ blin,
         float* __restrict__ out)
{
    extern __shared__ unsigned char smem[];
    const uint32_t sb = smem_u32(smem);
    const int tid = threadIdx.x, l = tid & 31, w = tid >> 5;   // w = col-warp 0..7
    const int cta = blockIdx.x, n0 = cta * MROWS;
    if (n0 >= 12800) return;

    for (int i = tid; i < 1024; i += NTHR) {
        int j = i >> 2, g = i & 3;
        ((float*)(smem + SM_BIAS))[i] = bih[g * 256 + j] + bhh[g * 256 + j];
    }
    for (int i = tid; i < 512; i += NTHR) ((float*)(smem + SM_WLIN))[i] = Wlin[i];

    // A init: gather x rows (clamped), fp16
    for (int idx = tid; idx < MROWS * 256; idx += NTHR) {
        int r = idx >> 8, c = idx & 255;
        int n = n0 + r; if (n > 12799) n = 12799;
        int bb = n / 1600, hw = n % 1600;
        float v = x[(size_t)bb * 409600 + (size_t)c * 1600 + hw];
        *(uint16_t*)(smem + SM_A + (r * 264 + c) * 2) =
            __half_as_ushort(__float2half_rn(v));
    }

    const uint32_t a_hi0 = sb + SM_A + (uint32_t)((l & 15) * 264) * 2
                         + (uint32_t)((l >> 4) & 1) * 16;
    const uint32_t b_lane = (uint32_t)((w * 32 + (l & 7) + ((l >> 4) & 1) * 8) * 80
                         + ((l >> 3) & 1) * 16);

    auto prefetch = [&](int img, int s, int buf) {
        const unsigned char* src = g_Wimg[img] + (size_t)s * 32768;
        uint32_t dst = sb + SM_W + (uint32_t)buf * 40960;
        #pragma unroll
        for (int i = 0; i < 8; ++i) {
            int o = i * NTHR + tid;
            int plane = o >> 10, rem = o & 1023;
            CPA16(dst + plane * 20480 + (rem >> 2) * 80 + (rem & 3) * 16,
                  src + (size_t)o * 16);
        }
        CPA_COMMIT();
    };

    const float bl0 = blin[0], bl1 = blin[1];
    prefetch(0, 0, 0);

    for (int t = 0; t < TSTEPS; ++t) {
        const int img = (t == 0) ? 0 : 1;
        float y0[3] = {0.f, 0.f, 0.f}, y1[3] = {0.f, 0.f, 0.f};

        for (int p = 0; p < 4; ++p) {
            float acc[3][4][4];
            #pragma unroll
            for (int mf = 0; mf < 3; ++mf)
                #pragma unroll
                for (int nf = 0; nf < 4; ++nf)
                    #pragma unroll
                    for (int r4 = 0; r4 < 4; ++r4) acc[mf][nf][r4] = 0.f;

            for (int c8 = 0; c8 < 8; ++c8) {
                int s = p * 8 + c8;
                __syncthreads();
                int ns = s + 1;
                if (!(t == 15 && ns == 32)) {
                    prefetch(ns < 32 ? img : 1, ns & 31, ns & 1);
                    CPA_WAIT1();
                } else {
                    CPA_WAIT0();
                }
                const uint32_t wb = sb + SM_W + (uint32_t)(s & 1) * 40960;
                #pragma unroll
                for (int kk = 0; kk < 2; ++kk) {
                    uint32_t ah[3][4];
                    #pragma unroll
                    for (int mf = 0; mf < 3; ++mf) {
                        uint32_t aa = a_hi0 + (uint32_t)(mf * 16 * 528)
                                    + (uint32_t)((c8 * 32 + kk * 16) * 2);
                        LDMX4(ah[mf], aa);
                    }
                    #pragma unroll
                    for (int np = 0; np < 2; ++np) {
                        uint32_t bh[4], bl[4];
                        uint32_t ba = b_lane + (uint32_t)(np * 16 * 80 + kk * 32);
                        LDMX4(bh, wb + ba);
                        LDMX4(bl, wb + 20480 + ba);
                        #pragma unroll
                        for (int mf = 0; mf < 3; ++mf)
                            #pragma unroll
                            for (int sub = 0; sub < 2; ++sub) {
                                float* d = acc[mf][np * 2 + sub];
                                MMA(d, ah[mf], bh[sub * 2], bh[sub * 2 + 1]);
                                MMA(d, ah[mf], bl[sub * 2], bl[sub * 2 + 1]);
                            }
                    }
                }
            }

            // ---- epilogue for pass p ----
            const bool ifl = ((l & 1) == 0);
            const float* sBias = (const float*)(smem + SM_BIAS);
            const float* sWl = (const float*)(smem + SM_WLIN);
            #pragma unroll
            for (int mf = 0; mf < 3; ++mf) {
                const size_t base = (((size_t)(cta * 8 + w) * 4 + p) * 3 + mf);
                const size_t xpb = base * 512;
                const size_t cxb = base * 128;
                #pragma unroll
                for (int nf = 0; nf < 4; ++nf) {
                    float* d = acc[mf][nf];
                    float p0, p1, p2, p3;
                    if (t == 0) {
                        int m0 = p * 256 + w * 32 + nf * 8 + 2 * (l & 3);
                        float bb0 = sBias[m0], bb1 = sBias[m0 + 1];
                        p0 = d[0] + bb0; p1 = d[1] + bb1; p2 = d[2] + bb0; p3 = d[3] + bb1;
                        float4 st = {p0, p1, p2, p3};
                        *(float4*)&g_xproj[xpb + (size_t)(nf * 32 + l) * 4] = st;
                    } else {
                        float4 xp = *(const float4*)&g_xproj[xpb + (size_t)(nf * 32 + l) * 4];
                        p0 = d[0] + xp.x; p1 = d[1] + xp.y; p2 = d[2] + xp.z; p3 = d[3] + xp.w;
                    }
                    float u0, u1, u2, u3;
                    if (ifl) { u0 = fsig(p0); u1 = fsig(p1); u2 = fsig(p2); u3 = fsig(p3); }
                    else     { u0 = ftanhx(p0); u1 = fsig(p1); u2 = ftanhx(p2); u3 = fsig(p3); }
                    float s0 = ifl ? u2 : u0;
                    float s1 = ifl ? u3 : u1;
                    float r0 = __shfl_xor_sync(0xffffffffu, s0, 1);
                    float r1 = __shfl_xor_sync(0xffffffffu, s1, 1);
                    float ig, fg, gg, og;
                    if (ifl) { ig = u0; fg = u1; gg = r0; og = r1; }
                    else     { ig = r0; fg = r1; gg = u2; og = u3; }
                    float cp = (t == 0) ? 0.f : g_cx[cxb + nf * 32 + l];
                    float cn = fmaf(fg, cp, ig * gg);
                    float h = og * ftanhx(cn);
                    float lh = (h > 0.f) ? h : 0.01f * h;
                    int jj = p * 64 + w * 8 + nf * 2 + ((l >> 1) & 1);
                    y0[mf] = fmaf(lh, sWl[jj], y0[mf]);
                    y1[mf] = fmaf(lh, sWl[256 + jj], y1[mf]);
                    if (t < 15) {
                        g_cx[cxb + nf * 32 + l] = cn;
                        g_hst[cxb + nf * 32 + l] = __half_as_ushort(__float2half_rn(h));
                    }
                }
            }
        } // passes

        // ---- head: reduce lane pairs (l^2), then 8 col-warps via SMEM ----
        #pragma unroll
        for (int mf = 0; mf < 3; ++mf) {
            y0[mf] += __shfl_xor_sync(0xffffffffu, y0[mf], 2);
            y1[mf] += __shfl_xor_sync(0xffffffffu, y1[mf], 2);
        }
        if ((l & 2) == 0) {
            #pragma unroll
            for (int mf = 0; mf < 3; ++mf) {
                int row = mf * 16 + (l >> 2) + 8 * (l & 1);
                ((float*)(smem + SM_HEAD))[(w * 48 + row) * 2 + 0] = y0[mf];
                ((float*)(smem + SM_HEAD))[(w * 48 + row) * 2 + 1] = y1[mf];
            }
        }
        __syncthreads();
        if (tid < 96) {
            int row = tid >> 1, o = tid & 1;
            int n = n0 + row;
            if (n < 12800) {
                float v = o ? bl1 : bl0;
                #pragma unroll
                for (int wcc = 0; wcc < 8; ++wcc)
                    v += ((float*)(smem + SM_HEAD))[(wcc * 48 + row) * 2 + o];
                out[(size_t)n * 32 + t * 2 + o] = v;
            }
        }

        // ---- rebuild A (fp16) from staged h ----
        if (t < 15) {
            const uint16_t* hs = g_hst + (size_t)cta * 12288;
            #pragma unroll
            for (int it = 0; it < 48; ++it) {
                int i = it * NTHR + tid;
                uint16_t hv = hs[i];
                int ll = i & 31, nf = (i >> 5) & 3, q = i >> 7;   // q = (w*4+p)*3+mf
                int mf = q % 3, wp = q / 3;
                int pp = wp & 3, ww = wp >> 2;
                int row = mf * 16 + (ll >> 2) + 8 * (ll & 1);
                int jj = pp * 64 + ww * 8 + nf * 2 + ((ll >> 1) & 1);
                *(uint16_t*)(smem + SM_A + (row * 264 + jj) * 2) = hv;
            }
        }
    } // t
}

extern "C" void kernel_launch(void* const* d_in, const int* in_sizes, int n_in,
                              void* d_out, int out_size) {
    const float* x    = (const float*)d_in[0];
    const float* Wih  = (const float*)d_in[3];
    const float* Whh  = (const float*)d_in[4];
    const float* bih  = (const float*)d_in[5];
    const float* bhh  = (const float*)d_in[6];
    const float* Wlin = (const float*)d_in[7];
    const float* blin = (const float*)d_in[8];
    (void)in_sizes; (void)n_in; (void)out_size;
    prep<<<512, 256>>>(Wih, Whh);
    cudaFuncSetAttribute(lstm_mma, cudaFuncAttributeMaxDynamicSharedMemorySize, SM_TOTAL);
    lstm_mma<<<NCTA, NTHR, SM_TOTAL>>>(x, bih, bhh, Wlin, blin, (float*)d_out);
}

// round 12
// speedup vs baseline: 3.6776x; 1.4051x over previous
#include <cuda_runtime.h>
#include <cuda_fp16.h>
#include <cstdint>

#define TSTEPS 16
#define NCTA   268
#define MROWS  48
#define NTHR   256

// ---- SMEM layout (bytes), 113408 total -> 2 CTAs/SM ----
#define SM_W      0                   // 4 bufs x (256 rows x 80B) hi-plane only
#define SM_A      81920               // [48][264] fp16
#define SM_BIAS   107264              // f32[1024] m'-order; HEAD overlays (3072B)
#define SM_WLIN   111360              // f32[512]
#define SM_TOTAL  113408
#define SM_HEAD   SM_BIAS

// ---- device scratch ----
__device__ unsigned char g_Wimg[2][524288];      // [ih/hh][32 chunks][16KB hi]
__device__ float    g_xproj[13172736];           // fragment-order xproj(+bias)
__device__ float    g_cx[3293184];
__device__ uint16_t g_hst[3293184];              // fp16 h staging

__device__ __forceinline__ uint32_t smem_u32(const void* p) {
    uint32_t a;
    asm("{ .reg .u64 t; cvta.to.shared.u64 t, %1; cvt.u32.u64 %0, t; }" : "=r"(a) : "l"(p));
    return a;
}
#define LDMX4(R, A) asm volatile( \
    "ldmatrix.sync.aligned.m8n8.x4.shared.b16 {%0,%1,%2,%3}, [%4];" \
    : "=r"((R)[0]), "=r"((R)[1]), "=r"((R)[2]), "=r"((R)[3]) : "r"(A))
#define MMA(D, A, B0, B1) asm volatile( \
    "mma.sync.aligned.m16n8k16.row.col.f32.f16.f16.f32 " \
    "{%0,%1,%2,%3}, {%4,%5,%6,%7}, {%8,%9}, {%0,%1,%2,%3};" \
    : "+f"((D)[0]), "+f"((D)[1]), "+f"((D)[2]), "+f"((D)[3]) \
    : "r"((A)[0]), "r"((A)[1]), "r"((A)[2]), "r"((A)[3]), "r"(B0), "r"(B1))
#define CPA16(S, G) asm volatile("cp.async.cg.shared.global [%0], [%1], 16;" :: "r"(S), "l"(G))
#define CPA_COMMIT() asm volatile("cp.async.commit_group;")
#define CPA_WAIT0()  asm volatile("cp.async.wait_group 0;")
#define CPA_WAIT2()  asm volatile("cp.async.wait_group 2;")

__device__ __forceinline__ float fsig(float x) { return __fdividef(1.0f, 1.0f + __expf(-x)); }
__device__ __forceinline__ float ftanhx(float x) { return fmaf(2.0f, fsig(2.0f * x), -1.0f); }
__device__ __forceinline__ uint32_t pkh(__half a, __half b) {
    return (uint32_t)__half_as_ushort(a) | ((uint32_t)__half_as_ushort(b) << 16);
}

// ---- prep: fp16 W image, gate-interleaved (m' = 4j+g), 16KB chunks ----
__global__ void prep(const float* __restrict__ Wih, const float* __restrict__ Whh) {
    int id = blockIdx.x * 256 + threadIdx.x;       // 131072
    int which = id >> 16, rest = id & 65535;
    int mp = rest >> 6, k4 = (rest & 63) * 4;
    int j = mp >> 2, g = mp & 3;
    const float* W = which ? Whh : Wih;
    float4 v = *(const float4*)&W[(size_t)(g * 256 + j) * 256 + k4];
    int p = mp >> 8, q = mp & 255;
    int ck = k4 >> 5, kk = k4 & 31;
    size_t off = (size_t)(p * 8 + ck) * 16384 + (size_t)q * 64 + (size_t)kk * 2;
    unsigned char* dst = g_Wimg[which] + off;
    *(uint32_t*)(dst)     = pkh(__float2half_rn(v.x), __float2half_rn(v.y));
    *(uint32_t*)(dst + 4) = pkh(__float2half_rn(v.z), __float2half_rn(v.w));
}

__global__ void __launch_bounds__(NTHR, 2)
lstm_mma(const float* __restrict__ x,
         const float* __restrict__ bih, const float* __restrict__ bhh,
         const float* __restrict__ Wlin, const float* __restrict__ blin,
         float* __restrict__ out)
{
    extern __shared__ unsigned char smem[];
    const uint32_t sb = smem_u32(smem);
    const int tid = threadIdx.x, l = tid & 31, w = tid >> 5;   // w = col-warp 0..7
    const int cta = blockIdx.x, n0 = cta * MROWS;
    if (n0 >= 12800) return;

    for (int i = tid; i < 1024; i += NTHR) {
        int j = i >> 2, g = i & 3;
        ((float*)(smem + SM_BIAS))[i] = bih[g * 256 + j] + bhh[g * 256 + j];
    }
    for (int i = tid; i < 512; i += NTHR) ((float*)(smem + SM_WLIN))[i] = Wlin[i];

    // A init: gather x rows (clamped), fp16
    for (int idx = tid; idx < MROWS * 256; idx += NTHR) {
        int r = idx >> 8, c = idx & 255;
        int n = n0 + r; if (n > 12799) n = 12799;
        int bb = n / 1600, hw = n % 1600;
        float v = x[(size_t)bb * 409600 + (size_t)c * 1600 + hw];
        *(uint16_t*)(smem + SM_A + (r * 264 + c) * 2) =
            __half_as_ushort(__float2half_rn(v));
    }

    const uint32_t a_hi0 = sb + SM_A + (uint32_t)((l & 15) * 264) * 2
                         + (uint32_t)((l >> 4) & 1) * 16;
    const uint32_t b_lane = (uint32_t)((w * 32 + (l & 7) + ((l >> 4) & 1) * 8) * 80
                         + ((l >> 3) & 1) * 16);

    auto prefetch = [&](int img, int s, int buf) {
        const unsigned char* src = g_Wimg[img] + (size_t)s * 16384;
        uint32_t dst = sb + SM_W + (uint32_t)buf * 20480;
        #pragma unroll
        for (int i = 0; i < 4; ++i) {
            int o = i * NTHR + tid;
            CPA16(dst + (o >> 2) * 80 + (o & 3) * 16, src + (size_t)o * 16);
        }
        CPA_COMMIT();
    };

    const float bl0 = blin[0], bl1 = blin[1];
    prefetch(0, 0, 0);
    prefetch(0, 1, 1);

    for (int t = 0; t < TSTEPS; ++t) {
        const int img = (t == 0) ? 0 : 1;
        float y0[3] = {0.f, 0.f, 0.f}, y1[3] = {0.f, 0.f, 0.f};

        for (int p = 0; p < 4; ++p) {
            float acc[3][4][4];
            #pragma unroll
            for (int mf = 0; mf < 3; ++mf)
                #pragma unroll
                for (int nf = 0; nf < 4; ++nf)
                    #pragma unroll
                    for (int r4 = 0; r4 < 4; ++r4) acc[mf][nf][r4] = 0.f;

            for (int cc = 0; cc < 4; ++cc) {
                int s0 = p * 8 + cc * 2;
                __syncthreads();
                if (!(t == 15 && s0 == 30)) {
                    int n1 = s0 + 2, n2 = s0 + 3;
                    prefetch(n1 < 32 ? img : 1, n1 & 31, n1 & 3);
                    prefetch(n2 < 32 ? img : 1, n2 & 31, n2 & 3);
                    CPA_WAIT2();
                } else {
                    CPA_WAIT0();
                }
                #pragma unroll
                for (int cs = 0; cs < 2; ++cs) {
                    int s = s0 + cs;
                    const uint32_t wb = sb + SM_W + (uint32_t)(s & 3) * 20480;
                    #pragma unroll
                    for (int kk = 0; kk < 2; ++kk) {
                        uint32_t ah[3][4];
                        #pragma unroll
                        for (int mf = 0; mf < 3; ++mf) {
                            uint32_t aa = a_hi0 + (uint32_t)(mf * 16 * 528)
                                        + (uint32_t)(((s & 7) * 32 + kk * 16) * 2);
                            LDMX4(ah[mf], aa);
                        }
                        #pragma unroll
                        for (int np = 0; np < 2; ++np) {
                            uint32_t bh[4];
                            LDMX4(bh, wb + b_lane + (uint32_t)(np * 16 * 80 + kk * 32));
                            #pragma unroll
                            for (int mf = 0; mf < 3; ++mf)
                                #pragma unroll
                                for (int sub = 0; sub < 2; ++sub)
                                    MMA(acc[mf][np * 2 + sub], ah[mf],
                                        bh[sub * 2], bh[sub * 2 + 1]);
                        }
                    }
                }
            }

            // ---- epilogue for pass p ----
            const bool ifl = ((l & 1) == 0);
            const float* sBias = (const float*)(smem + SM_BIAS);
            const float* sWl = (const float*)(smem + SM_WLIN);
            #pragma unroll
            for (int mf = 0; mf < 3; ++mf) {
                const size_t base = (((size_t)(cta * 8 + w) * 4 + p) * 3 + mf);
                const size_t xpb = base * 512;
                const size_t cxb = base * 128;
                #pragma unroll
                for (int nf = 0; nf < 4; ++nf) {
                    float* d = acc[mf][nf];
                    float p0, p1, p2, p3;
                    if (t == 0) {
                        int m0 = p * 256 + w * 32 + nf * 8 + 2 * (l & 3);
                        float bb0 = sBias[m0], bb1 = sBias[m0 + 1];
                        p0 = d[0] + bb0; p1 = d[1] + bb1; p2 = d[2] + bb0; p3 = d[3] + bb1;
                        float4 st = {p0, p1, p2, p3};
                        *(float4*)&g_xproj[xpb + (size_t)(nf * 32 + l) * 4] = st;
                    } else {
                        float4 xp = *(const float4*)&g_xproj[xpb + (size_t)(nf * 32 + l) * 4];
                        p0 = d[0] + xp.x; p1 = d[1] + xp.y; p2 = d[2] + xp.z; p3 = d[3] + xp.w;
                    }
                    float u0, u1, u2, u3;
                    if (ifl) { u0 = fsig(p0); u1 = fsig(p1); u2 = fsig(p2); u3 = fsig(p3); }
                    else     { u0 = ftanhx(p0); u1 = fsig(p1); u2 = ftanhx(p2); u3 = fsig(p3); }
                    float s0 = ifl ? u2 : u0;
                    float s1 = ifl ? u3 : u1;
                    float r0 = __shfl_xor_sync(0xffffffffu, s0, 1);
                    float r1 = __shfl_xor_sync(0xffffffffu, s1, 1);
                    float ig, fg, gg, og;
                    if (ifl) { ig = u0; fg = u1; gg = r0; og = r1; }
                    else     { ig = r0; fg = r1; gg = u2; og = u3; }
                    float cp = (t == 0) ? 0.f : g_cx[cxb + nf * 32 + l];
                    float cn = fmaf(fg, cp, ig * gg);
                    float h = og * ftanhx(cn);
                    float lh = (h > 0.f) ? h : 0.01f * h;
                    int jj = p * 64 + w * 8 + nf * 2 + ((l >> 1) & 1);
                    y0[mf] = fmaf(lh, sWl[jj], y0[mf]);
                    y1[mf] = fmaf(lh, sWl[256 + jj], y1[mf]);
                    if (t < 15) {
                        g_cx[cxb + nf * 32 + l] = cn;
                        g_hst[cxb + nf * 32 + l] = __half_as_ushort(__float2half_rn(h));
                    }
                }
            }
        } // passes

        // ---- head: reduce lane pairs (l^2), then 8 col-warps via SMEM ----
        #pragma unroll
        for (int mf = 0; mf < 3; ++mf) {
            y0[mf] += __shfl_xor_sync(0xffffffffu, y0[mf], 2);
            y1[mf] += __shfl_xor_sync(0xffffffffu, y1[mf], 2);
        }
        if ((l & 2) == 0) {
            #pragma unroll
            for (int mf = 0; mf < 3; ++mf) {
                int row = mf * 16 + (l >> 2) + 8 * (l & 1);
                ((float*)(smem + SM_HEAD))[(w * 48 + row) * 2 + 0] = y0[mf];
                ((float*)(smem + SM_HEAD))[(w * 48 + row) * 2 + 1] = y1[mf];
            }
        }
        __syncthreads();
        if (tid < 96) {
            int row = tid >> 1, o = tid & 1;
            int n = n0 + row;
            if (n < 12800) {
                float v = o ? bl1 : bl0;
                #pragma unroll
                for (int wcc = 0; wcc < 8; ++wcc)
                    v += ((float*)(smem + SM_HEAD))[(wcc * 48 + row) * 2 + o];
                out[(size_t)n * 32 + t * 2 + o] = v;
            }
        }

        // ---- rebuild A (fp16) from staged h ----
        if (t < 15) {
            const uint16_t* hs = g_hst + (size_t)cta * 12288;
            #pragma unroll
            for (int it = 0; it < 48; ++it) {
                int i = it * NTHR + tid;
                uint16_t hv = hs[i];
                int ll = i & 31, nf = (i >> 5) & 3, q = i >> 7;   // q = (w*4+p)*3+mf
                int mf = q % 3, wp = q / 3;
                int pp = wp & 3, ww = wp >> 2;
                int row = mf * 16 + (ll >> 2) + 8 * (ll & 1);
                int jj = pp * 64 + ww * 8 + nf * 2 + ((ll >> 1) & 1);
                *(uint16_t*)(smem + SM_A + (row * 264 + jj) * 2) = hv;
            }
        }
    } // t
}

extern "C" void kernel_launch(void* const* d_in, const int* in_sizes, int n_in,
                              void* d_out, int out_size) {
    const float* x    = (const float*)d_in[0];
    const float* Wih  = (const float*)d_in[3];
    const float* Whh  = (const float*)d_in[4];
    const float* bih  = (const float*)d_in[5];
    const float* bhh  = (const float*)d_in[6];
    const float* Wlin = (const float*)d_in[7];
    const float* blin = (const float*)d_in[8];
    (void)in_sizes; (void)n_in; (void)out_size;
    prep<<<512, 256>>>(Wih, Whh);
    cudaFuncSetAttribute(lstm_mma, cudaFuncAttributeMaxDynamicSharedMemorySize, SM_TOTAL);
    lstm_mma<<<NCTA, NTHR, SM_TOTAL>>>(x, bih, bhh, Wlin, blin, (float*)d_out);
}

// round 15
// speedup vs baseline: 4.0386x; 1.0982x over previous
#include <cuda_runtime.h>
#include <cuda_fp16.h>
#include <cstdint>

#define TSTEPS 16
#define NCTA   400
#define MROWS  32
#define NTHR   256

// ---- SMEM layout (bytes), 64000 total -> 3 CTAs/SM ----
#define SM_W      0                   // 2 bufs x (256 rows x 80B) hi-plane
#define SM_A      40960               // [32][264] fp16
#define SM_BIAS   57856               // f32[1024] m'-order; HEAD overlays (2048B)
#define SM_WLIN   61952               // f32[512]
#define SM_TOTAL  64000
#define SM_HEAD   SM_BIAS

// ---- device scratch ----
__device__ unsigned char g_Wimg[2][524288];      // [ih/hh][32 chunks][16KB]
__device__ float    g_xproj[13107200];           // fragment-order xproj(+bias)
__device__ float    g_cx[3276800];
__device__ uint16_t g_hst[3276800];              // fp16 h staging

__device__ __forceinline__ uint32_t smem_u32(const void* p) {
    uint32_t a;
    asm("{ .reg .u64 t; cvta.to.shared.u64 t, %1; cvt.u32.u64 %0, t; }" : "=r"(a) : "l"(p));
    return a;
}
#define LDMX4(R, A) asm volatile( \
    "ldmatrix.sync.aligned.m8n8.x4.shared.b16 {%0,%1,%2,%3}, [%4];" \
    : "=r"((R)[0]), "=r"((R)[1]), "=r"((R)[2]), "=r"((R)[3]) : "r"(A))
#define MMA(D, A, B0, B1) asm volatile( \
    "mma.sync.aligned.m16n8k16.row.col.f32.f16.f16.f32 " \
    "{%0,%1,%2,%3}, {%4,%5,%6,%7}, {%8,%9}, {%0,%1,%2,%3};" \
    : "+f"((D)[0]), "+f"((D)[1]), "+f"((D)[2]), "+f"((D)[3]) \
    : "r"((A)[0]), "r"((A)[1]), "r"((A)[2]), "r"((A)[3]), "r"(B0), "r"(B1))
#define CPA16(S, G) asm volatile("cp.async.cg.shared.global [%0], [%1], 16;" :: "r"(S), "l"(G))
#define CPA_COMMIT() asm volatile("cp.async.commit_group;")
#define CPA_WAIT0()  asm volatile("cp.async.wait_group 0;")

__device__ __forceinline__ float fsig(float x) { return __fdividef(1.0f, 1.0f + __expf(-x)); }
__device__ __forceinline__ float ftanhx(float x) { return fmaf(2.0f, fsig(2.0f * x), -1.0f); }
__device__ __forceinline__ uint32_t pkh(__half a, __half b) {
    return (uint32_t)__half_as_ushort(a) | ((uint32_t)__half_as_ushort(b) << 16);
}

// ---- prep: fp16 W image, gate-interleaved (m' = 4j+g), 16KB chunks ----
__global__ void prep(const float* __restrict__ Wih, const float* __restrict__ Whh) {
    int id = blockIdx.x * 256 + threadIdx.x;       // 131072
    int which = id >> 16, rest = id & 65535;
    int mp = rest >> 6, k4 = (rest & 63) * 4;
    int j = mp >> 2, g = mp & 3;
    const float* W = which ? Whh : Wih;
    float4 v = *(const float4*)&W[(size_t)(g * 256 + j) * 256 + k4];
    int p = mp >> 8, q = mp & 255;
    int ck = k4 >> 5, kk = k4 & 31;
    size_t off = (size_t)(p * 8 + ck) * 16384 + (size_t)q * 64 + (size_t)kk * 2;
    unsigned char* dst = g_Wimg[which] + off;
    *(uint32_t*)(dst)     = pkh(__float2half_rn(v.x), __float2half_rn(v.y));
    *(uint32_t*)(dst + 4) = pkh(__float2half_rn(v.z), __float2half_rn(v.w));
}

__global__ void __launch_bounds__(NTHR, 3)
lstm_mma(const float* __restrict__ x,
         const float* __restrict__ bih, const float* __restrict__ bhh,
         const float* __restrict__ Wlin, const float* __restrict__ blin,
         float* __restrict__ out)
{
    extern __shared__ unsigned char smem[];
    const uint32_t sb = smem_u32(smem);
    const int tid = threadIdx.x, l = tid & 31, w = tid >> 5;   // w = col-warp 0..7
    const int cta = blockIdx.x, n0 = cta * MROWS;

    for (int i = tid; i < 1024; i += NTHR) {
        int j = i >> 2, g = i & 3;
        ((float*)(smem + SM_BIAS))[i] = bih[g * 256 + j] + bhh[g * 256 + j];
    }
    for (int i = tid; i < 512; i += NTHR) ((float*)(smem + SM_WLIN))[i] = Wlin[i];

    // A init: gather x rows, fp16 (400*32 = 12800 exactly, no clamp)
    for (int idx = tid; idx < MROWS * 256; idx += NTHR) {
        int r = idx >> 8, c = idx & 255;
        int n = n0 + r;
        int bb = n / 1600, hw = n % 1600;
        float v = x[(size_t)bb * 409600 + (size_t)c * 1600 + hw];
        *(uint16_t*)(smem + SM_A + (r * 264 + c) * 2) =
            __half_as_ushort(__float2half_rn(v));
    }

    const uint32_t a_hi0 = sb + SM_A + (uint32_t)((l & 15) * 264) * 2
                         + (uint32_t)((l >> 4) & 1) * 16;
    const uint32_t b_lane = (uint32_t)((w * 32 + (l & 7) + ((l >> 4) & 1) * 8) * 80
                         + ((l >> 3) & 1) * 16);

    auto prefetch = [&](int img, int s, int buf) {
        const unsigned char* src = g_Wimg[img] + (size_t)s * 16384;
        uint32_t dst = sb + SM_W + (uint32_t)buf * 20480;
        #pragma unroll
        for (int i = 0; i < 4; ++i) {
            int o = i * NTHR + tid;
            CPA16(dst + (o >> 2) * 80 + (o & 3) * 16, src + (size_t)o * 16);
        }
        CPA_COMMIT();
    };

    const float bl0 = blin[0], bl1 = blin[1];
    prefetch(0, 0, 0);

    for (int t = 0; t < TSTEPS; ++t) {
        const int img = (t == 0) ? 0 : 1;
        float y0[2] = {0.f, 0.f}, y1[2] = {0.f, 0.f};

        for (int p = 0; p < 4; ++p) {
            float acc[2][4][4];
            #pragma unroll
            for (int mf = 0; mf < 2; ++mf)
                #pragma unroll
                for (int nf = 0; nf < 4; ++nf)
                    #pragma unroll
                    for (int r4 = 0; r4 < 4; ++r4) acc[mf][nf][r4] = 0.f;

            for (int c8 = 0; c8 < 8; ++c8) {
                int s = p * 8 + c8;
                CPA_WAIT0();          // chunk s landed (issued last iteration)
                __syncthreads();      // all warps done reading the other buffer
                int ns = s + 1;
                if (!(t == 15 && ns == 32))
                    prefetch(ns < 32 ? img : 1, ns & 31, ns & 1);
                const uint32_t wb = sb + SM_W + (uint32_t)(s & 1) * 20480;
                #pragma unroll
                for (int kk = 0; kk < 2; ++kk) {
                    uint32_t ah[2][4];
                    #pragma unroll
                    for (int mf = 0; mf < 2; ++mf) {
                        uint32_t aa = a_hi0 + (uint32_t)(mf * 16 * 528)
                                    + (uint32_t)((c8 * 32 + kk * 16) * 2);
                        LDMX4(ah[mf], aa);
                    }
                    #pragma unroll
                    for (int np = 0; np < 2; ++np) {
                        uint32_t bh[4];
                        LDMX4(bh, wb + b_lane + (uint32_t)(np * 16 * 80 + kk * 32));
                        #pragma unroll
                        for (int mf = 0; mf < 2; ++mf)
                            #pragma unroll
                            for (int sub = 0; sub < 2; ++sub)
                                MMA(acc[mf][np * 2 + sub], ah[mf],
                                    bh[sub * 2], bh[sub * 2 + 1]);
                    }
                }
            }

            // ---- epilogue for pass p ----
            const bool ifl = ((l & 1) == 0);
            const float* sBias = (const float*)(smem + SM_BIAS);
            const float* sWl = (const float*)(smem + SM_WLIN);
            #pragma unroll
            for (int mf = 0; mf < 2; ++mf) {
                const size_t base = (((size_t)(cta * 8 + w) * 4 + p) * 2 + mf);
                const size_t xpb = base * 512;
                const size_t cxb = base * 128;
                #pragma unroll
                for (int nf = 0; nf < 4; ++nf) {
                    float* d = acc[mf][nf];
                    float p0, p1, p2, p3;
                    if (t == 0) {
                        int m0 = p * 256 + w * 32 + nf * 8 + 2 * (l & 3);
                        float bb0 = sBias[m0], bb1 = sBias[m0 + 1];
                        p0 = d[0] + bb0; p1 = d[1] + bb1; p2 = d[2] + bb0; p3 = d[3] + bb1;
                        float4 st = {p0, p1, p2, p3};
                        *(float4*)&g_xproj[xpb + (size_t)(nf * 32 + l) * 4] = st;
                    } else {
                        float4 xp = *(const float4*)&g_xproj[xpb + (size_t)(nf * 32 + l) * 4];
                        p0 = d[0] + xp.x; p1 = d[1] + xp.y; p2 = d[2] + xp.z; p3 = d[3] + xp.w;
                    }
                    float u0, u1, u2, u3;
                    if (ifl) { u0 = fsig(p0); u1 = fsig(p1); u2 = fsig(p2); u3 = fsig(p3); }
                    else     { u0 = ftanhx(p0); u1 = fsig(p1); u2 = ftanhx(p2); u3 = fsig(p3); }
                    float s0 = ifl ? u2 : u0;
                    float s1 = ifl ? u3 : u1;
                    float r0 = __shfl_xor_sync(0xffffffffu, s0, 1);
                    float r1 = __shfl_xor_sync(0xffffffffu, s1, 1);
                    float ig, fg, gg, og;
                    if (ifl) { ig = u0; fg = u1; gg = r0; og = r1; }
                    else     { ig = r0; fg = r1; gg = u2; og = u3; }
                    float cp = (t == 0) ? 0.f : g_cx[cxb + nf * 32 + l];
                    float cn = fmaf(fg, cp, ig * gg);
                    float h = og * ftanhx(cn);
                    float lh = (h > 0.f) ? h : 0.01f * h;
                    int jj = p * 64 + w * 8 + nf * 2 + ((l >> 1) & 1);
                    y0[mf] = fmaf(lh, sWl[jj], y0[mf]);
                    y1[mf] = fmaf(lh, sWl[256 + jj], y1[mf]);
                    if (t < 15) {
                        g_cx[cxb + nf * 32 + l] = cn;
                        g_hst[cxb + nf * 32 + l] = __half_as_ushort(__float2half_rn(h));
                    }
                }
            }
        } // passes

        // ---- head: reduce lane pairs (l^2), then 8 col-warps via SMEM ----
        #pragma unroll
        for (int mf = 0; mf < 2; ++mf) {
            y0[mf] += __shfl_xor_sync(0xffffffffu, y0[mf], 2);
            y1[mf] += __shfl_xor_sync(0xffffffffu, y1[mf], 2);
        }
        if ((l & 2) == 0) {
            #pragma unroll
            for (int mf = 0; mf < 2; ++mf) {
                int row = mf * 16 + (l >> 2) + 8 * (l & 1);
                ((float*)(smem + SM_HEAD))[(w * 32 + row) * 2 + 0] = y0[mf];
                ((float*)(smem + SM_HEAD))[(w * 32 + row) * 2 + 1] = y1[mf];
            }
        }
        __syncthreads();
        if (tid < 64) {
            int row = tid >> 1, o = tid & 1;
            float v = o ? bl1 : bl0;
            #pragma unroll
            for (int wcc = 0; wcc < 8; ++wcc)
                v += ((float*)(smem + SM_HEAD))[(wcc * 32 + row) * 2 + o];
            out[(size_t)(n0 + row) * 32 + t * 2 + o] = v;
        }

        // ---- rebuild A (fp16) from staged h ----
        if (t < 15) {
            const uint16_t* hs = g_hst + (size_t)cta * 8192;
            #pragma unroll
            for (int it = 0; it < 32; ++it) {
                int i = it * NTHR + tid;
                uint16_t hv = hs[i];
                int ll = i & 31, nf = (i >> 5) & 3, q = i >> 7;   // q = (w*4+p)*2+mf
                int mf = q & 1, wp = q >> 1;
                int pp = wp & 3, ww = wp >> 2;
                int row = mf * 16 + (ll >> 2) + 8 * (ll & 1);
                int jj = pp * 64 + ww * 8 + nf * 2 + ((ll >> 1) & 1);
                *(uint16_t*)(smem + SM_A + (row * 264 + jj) * 2) = hv;
            }
        }
    } // t
}

extern "C" void kernel_launch(void* const* d_in, const int* in_sizes, int n_in,
                              void* d_out, int out_size) {
    const float* x    = (const float*)d_in[0];
    const float* Wih  = (const float*)d_in[3];
    const float* Whh  = (const float*)d_in[4];
    const float* bih  = (const float*)d_in[5];
    const float* bhh  = (const float*)d_in[6];
    const float* Wlin = (const float*)d_in[7];
    const float* blin = (const float*)d_in[8];
    (void)in_sizes; (void)n_in; (void)out_size;
    prep<<<512, 256>>>(Wih, Whh);
    cudaFuncSetAttribute(lstm_mma, cudaFuncAttributeMaxDynamicSharedMemorySize, SM_TOTAL);
    lstm_mma<<<NCTA, NTHR, SM_TOTAL>>>(x, bih, bhh, Wlin, blin, (float*)d_out);
}

// round 16
// speedup vs baseline: 6.1320x; 1.5183x over previous
#include <cuda_runtime.h>
#include <cuda_fp16.h>
#include <cstdint>

#define TSTEPS 16
#define NCTA   400
#define MROWS  32
#define NTHR   256

// ---- SMEM layout (bytes): W no longer staged in SMEM at all ----
#define SM_A      0                   // [32][264] fp16
#define SM_BIAS   16896               // f32[1024] m'-order; HEAD overlays first 2048B
#define SM_WLIN   20992               // f32[512]
#define SM_TOTAL  23040
#define SM_HEAD   SM_BIAS

// ---- device scratch ----
// W images in MMA B-fragment order:
//   offset = s*16384 + w*2048 + (kk*2+np)*512 + lane*16
//   lane 16B = {B0(sub0), B1(sub0), B0(sub1), B1(sub1)}
__device__ unsigned char g_Wimg[2][524288];
__device__ float    g_xproj[13107200];           // fragment-order xproj(+bias)
__device__ float    g_cx[3276800];
__device__ uint16_t g_hst[3276800];              // fp16 h staging

__device__ __forceinline__ uint32_t smem_u32(const void* p) {
    uint32_t a;
    asm("{ .reg .u64 t; cvta.to.shared.u64 t, %1; cvt.u32.u64 %0, t; }" : "=r"(a) : "l"(p));
    return a;
}
#define LDMX4(R, A) asm volatile( \
    "ldmatrix.sync.aligned.m8n8.x4.shared.b16 {%0,%1,%2,%3}, [%4];" \
    : "=r"((R)[0]), "=r"((R)[1]), "=r"((R)[2]), "=r"((R)[3]) : "r"(A))
#define MMA(D, A, B0, B1) asm volatile( \
    "mma.sync.aligned.m16n8k16.row.col.f32.f16.f16.f32 " \
    "{%0,%1,%2,%3}, {%4,%5,%6,%7}, {%8,%9}, {%0,%1,%2,%3};" \
    : "+f"((D)[0]), "+f"((D)[1]), "+f"((D)[2]), "+f"((D)[3]) \
    : "r"((A)[0]), "r"((A)[1]), "r"((A)[2]), "r"((A)[3]), "r"(B0), "r"(B1))

__device__ __forceinline__ float fsig(float x) { return __fdividef(1.0f, 1.0f + __expf(-x)); }
__device__ __forceinline__ float ftanhx(float x) { return fmaf(2.0f, fsig(2.0f * x), -1.0f); }
__device__ __forceinline__ uint32_t pkh(__half a, __half b) {
    return (uint32_t)__half_as_ushort(a) | ((uint32_t)__half_as_ushort(b) << 16);
}

// ---- prep: fp16 W in fragment order (PTX m16n8k16 .col B layout) ----
__global__ void prep(const float* __restrict__ Wih, const float* __restrict__ Whh) {
    int id = blockIdx.x * 256 + threadIdx.x;       // 65536 threads
    int which = id >> 15, rest = id & 32767;
    int s  = rest >> 10;           // chunk 0..31 (p = s>>3, k-block = s&7)
    int w  = (rest >> 7) & 7;      // col-warp
    int kk = (rest >> 6) & 1;
    int np = (rest >> 5) & 1;
    int l  = rest & 31;            // lane
    const float* W = which ? Whh : Wih;
    int p  = s >> 3;
    int kb = (s & 7) * 32 + kk * 16 + (l & 3) * 2;
    uint32_t vals[4];
    #pragma unroll
    for (int sub = 0; sub < 2; ++sub) {
        int mp  = p * 256 + w * 32 + np * 16 + sub * 8 + (l >> 2);  // m' = 4j+g
        int row = (mp & 3) * 256 + (mp >> 2);                       // original W row
        const float* wr = W + (size_t)row * 256 + kb;
        vals[sub * 2 + 0] = pkh(__float2half_rn(wr[0]), __float2half_rn(wr[1]));
        vals[sub * 2 + 1] = pkh(__float2half_rn(wr[8]), __float2half_rn(wr[9]));
    }
    *(uint4*)(g_Wimg[which] + (size_t)s * 16384 + w * 2048
              + (kk * 2 + np) * 512 + l * 16) = *(uint4*)vals;
}

__global__ void __launch_bounds__(NTHR, 3)
lstm_mma(const float* __restrict__ x,
         const float* __restrict__ bih, const float* __restrict__ bhh,
         const float* __restrict__ Wlin, const float* __restrict__ blin,
         float* __restrict__ out)
{
    extern __shared__ unsigned char smem[];
    const uint32_t sb = smem_u32(smem);
    const int tid = threadIdx.x, l = tid & 31, w = tid >> 5;   // w = col-warp 0..7
    const int cta = blockIdx.x, n0 = cta * MROWS;

    for (int i = tid; i < 1024; i += NTHR) {
        int j = i >> 2, g = i & 3;
        ((float*)(smem + SM_BIAS))[i] = bih[g * 256 + j] + bhh[g * 256 + j];
    }
    for (int i = tid; i < 512; i += NTHR) ((float*)(smem + SM_WLIN))[i] = Wlin[i];

    // A init: gather x rows, fp16 (400*32 = 12800 exactly)
    for (int idx = tid; idx < MROWS * 256; idx += NTHR) {
        int r = idx >> 8, c = idx & 255;
        int n = n0 + r;
        int bb = n / 1600, hw = n % 1600;
        float v = x[(size_t)bb * 409600 + (size_t)c * 1600 + hw];
        *(uint16_t*)(smem + SM_A + (r * 264 + c) * 2) =
            __half_as_ushort(__float2half_rn(v));
    }
    __syncthreads();

    const uint32_t a_hi0 = sb + SM_A + (uint32_t)((l & 15) * 264) * 2
                         + (uint32_t)((l >> 4) & 1) * 16;
    const uint32_t wl_off = (uint32_t)(w * 2048 + l * 16);
    const float bl0 = blin[0], bl1 = blin[1];

    for (int t = 0; t < TSTEPS; ++t) {
        const unsigned char* wimg = g_Wimg[(t == 0) ? 0 : 1] + wl_off;
        float y0[2] = {0.f, 0.f}, y1[2] = {0.f, 0.f};

        for (int p = 0; p < 4; ++p) {
            float acc[2][4][4];
            #pragma unroll
            for (int mf = 0; mf < 2; ++mf)
                #pragma unroll
                for (int nf = 0; nf < 4; ++nf)
                    #pragma unroll
                    for (int r4 = 0; r4 < 4; ++r4) acc[mf][nf][r4] = 0.f;

            for (int c8 = 0; c8 < 8; ++c8) {
                int s = p * 8 + c8;
                const unsigned char* wc = wimg + (size_t)s * 16384;
                // 4 fragment loads (kk*2+np), straight from L2-resident image
                uint4 bq0 = *(const uint4*)(wc);
                uint4 bq1 = *(const uint4*)(wc + 512);
                uint4 bq2 = *(const uint4*)(wc + 1024);
                uint4 bq3 = *(const uint4*)(wc + 1536);
                #pragma unroll
                for (int kk = 0; kk < 2; ++kk) {
                    uint32_t ah[2][4];
                    #pragma unroll
                    for (int mf = 0; mf < 2; ++mf) {
                        uint32_t aa = a_hi0 + (uint32_t)(mf * 16 * 528)
                                    + (uint32_t)((c8 * 32 + kk * 16) * 2);
                        LDMX4(ah[mf], aa);
                    }
                    uint4 bA = kk ? bq2 : bq0;   // np = 0
                    uint4 bB = kk ? bq3 : bq1;   // np = 1
                    #pragma unroll
                    for (int mf = 0; mf < 2; ++mf) {
                        MMA(acc[mf][0], ah[mf], bA.x, bA.y);
                        MMA(acc[mf][1], ah[mf], bA.z, bA.w);
                        MMA(acc[mf][2], ah[mf], bB.x, bB.y);
                        MMA(acc[mf][3], ah[mf], bB.z, bB.w);
                    }
                }
            }

            // ---- epilogue for pass p (byte-identical math to R12/R15) ----
            const bool ifl = ((l & 1) == 0);
            const float* sBias = (const float*)(smem + SM_BIAS);
            const float* sWl = (const float*)(smem + SM_WLIN);
            #pragma unroll
            for (int mf = 0; mf < 2; ++mf) {
                const size_t base = (((size_t)(cta * 8 + w) * 4 + p) * 2 + mf);
                const size_t xpb = base * 512;
                const size_t cxb = base * 128;
                #pragma unroll
                for (int nf = 0; nf < 4; ++nf) {
                    float* d = acc[mf][nf];
                    float p0, p1, p2, p3;
                    if (t == 0) {
                        int m0 = p * 256 + w * 32 + nf * 8 + 2 * (l & 3);
                        float bb0 = sBias[m0], bb1 = sBias[m0 + 1];
                        p0 = d[0] + bb0; p1 = d[1] + bb1; p2 = d[2] + bb0; p3 = d[3] + bb1;
                        float4 st = {p0, p1, p2, p3};
                        *(float4*)&g_xproj[xpb + (size_t)(nf * 32 + l) * 4] = st;
                    } else {
                        float4 xp = *(const float4*)&g_xproj[xpb + (size_t)(nf * 32 + l) * 4];
                        p0 = d[0] + xp.x; p1 = d[1] + xp.y; p2 = d[2] + xp.z; p3 = d[3] + xp.w;
                    }
                    float u0, u1, u2, u3;
                    if (ifl) { u0 = fsig(p0); u1 = fsig(p1); u2 = fsig(p2); u3 = fsig(p3); }
                    else     { u0 = ftanhx(p0); u1 = fsig(p1); u2 = ftanhx(p2); u3 = fsig(p3); }
                    float s0 = ifl ? u2 : u0;
                    float s1 = ifl ? u3 : u1;
                    float r0 = __shfl_xor_sync(0xffffffffu, s0, 1);
                    float r1 = __shfl_xor_sync(0xffffffffu, s1, 1);
                    float ig, fg, gg, og;
                    if (ifl) { ig = u0; fg = u1; gg = r0; og = r1; }
                    else     { ig = r0; fg = r1; gg = u2; og = u3; }
                    float cp = (t == 0) ? 0.f : g_cx[cxb + nf * 32 + l];
                    float cn = fmaf(fg, cp, ig * gg);
                    float h = og * ftanhx(cn);
                    float lh = (h > 0.f) ? h : 0.01f * h;
                    int jj = p * 64 + w * 8 + nf * 2 + ((l >> 1) & 1);
                    y0[mf] = fmaf(lh, sWl[jj], y0[mf]);
                    y1[mf] = fmaf(lh, sWl[256 + jj], y1[mf]);
                    if (t < 15) {
                        g_cx[cxb + nf * 32 + l] = cn;
                        g_hst[cxb + nf * 32 + l] = __half_as_ushort(__float2half_rn(h));
                    }
                }
            }
        } // passes

        // ---- head: reduce lane pairs (l^2), then 8 col-warps via SMEM ----
        #pragma unroll
        for (int mf = 0; mf < 2; ++mf) {
            y0[mf] += __shfl_xor_sync(0xffffffffu, y0[mf], 2);
            y1[mf] += __shfl_xor_sync(0xffffffffu, y1[mf], 2);
        }
        if ((l & 2) == 0) {
            #pragma unroll
            for (int mf = 0; mf < 2; ++mf) {
                int row = mf * 16 + (l >> 2) + 8 * (l & 1);
                ((float*)(smem + SM_HEAD))[(w * 32 + row) * 2 + 0] = y0[mf];
                ((float*)(smem + SM_HEAD))[(w * 32 + row) * 2 + 1] = y1[mf];
            }
        }
        __syncthreads();   // head ready; also: all warps done reading A this step
        if (tid < 64) {
            int row = tid >> 1, o = tid & 1;
            float v = o ? bl1 : bl0;
            #pragma unroll
            for (int wcc = 0; wcc < 8; ++wcc)
                v += ((float*)(smem + SM_HEAD))[(wcc * 32 + row) * 2 + o];
            out[(size_t)(n0 + row) * 32 + t * 2 + o] = v;
        }

        // ---- rebuild A (fp16) from staged h ----
        if (t < 15) {
            const uint16_t* hs = g_hst + (size_t)cta * 8192;
            #pragma unroll
            for (int it = 0; it < 32; ++it) {
                int i = it * NTHR + tid;
                uint16_t hv = hs[i];
                int ll = i & 31, nf = (i >> 5) & 3, q = i >> 7;   // q = (w*4+p)*2+mf
                int mf = q & 1, wp = q >> 1;
                int pp = wp & 3, ww = wp >> 2;
                int row = mf * 16 + (ll >> 2) + 8 * (ll & 1);
                int jj = pp * 64 + ww * 8 + nf * 2 + ((ll >> 1) & 1);
                *(uint16_t*)(smem + SM_A + (row * 264 + jj) * 2) = hv;
            }
            __syncthreads();   // A rebuilt before next step's mma
        }
    } // t
}

extern "C" void kernel_launch(void* const* d_in, const int* in_sizes, int n_in,
                              void* d_out, int out_size) {
    const float* x    = (const float*)d_in[0];
    const float* Wih  = (const float*)d_in[3];
    const float* Whh  = (const float*)d_in[4];
    const float* bih  = (const float*)d_in[5];
    const float* bhh  = (const float*)d_in[6];
    const float* Wlin = (const float*)d_in[7];
    const float* blin = (const float*)d_in[8];
    (void)in_sizes; (void)n_in; (void)out_size;
    prep<<<256, 256>>>(Wih, Whh);
    cudaFuncSetAttribute(lstm_mma, cudaFuncAttributeMaxDynamicSharedMemorySize, SM_TOTAL);
    lstm_mma<<<NCTA, NTHR, SM_TOTAL>>>(x, bih, bhh, Wlin, blin, (float*)d_out);
}